// round 15
// baseline (speedup 1.0000x reference)
#include <cuda_runtime.h>
#include <cuda_fp16.h>
#include <stdint.h>
#include <math.h>

#define NN 100000
#define NG 256
#define MAXE 3400000
#define NB_SCAN ((NN + 1023) / 1024)

// ---------------- scratch (device globals; no allocations allowed) ----------
__device__ __half g_hA[(size_t)NN * 200];
__device__ __half g_hB[(size_t)NN * 200];
__device__ __half g_z [(size_t)NN * 200];
__device__ __half g_y [(size_t)NN * 200];
__device__ __half g_xh[(size_t)NN * 16];
__device__ __half g_aggh[(size_t)NN * 16];
__device__ __half g_w16[8 * 200 * 200];
__device__ __half g_w1[2 * 200 * 16];
__device__ float g_invdeg[NN];
__device__ float g_pool[NG * 1000];
__device__ float g_m1[NG * 500];
__device__ float g_m2[NG * 250];
__device__ int   g_gstart[NG + 1];
__device__ int   g_gcnt[NG];
__device__ float g_ginv[NG];
__device__ int   g_rowcnt[NN];
__device__ int   g_rowptr[NN + 1];
__device__ int   g_cursor[NN];
__device__ int   g_col[MAXE];
__device__ int   g_bsum[NB_SCAN];
__device__ int   g_boff[NB_SCAN];

// ---------------- small helpers ----------------------------------------------
__device__ __forceinline__ void cp16(uint32_t saddr, const void* gaddr, int sz) {
    asm volatile("cp.async.cg.shared.global [%0], [%1], 16, %2;"
                 :: "r"(saddr), "l"(gaddr), "r"(sz));
}
__device__ __forceinline__ void cp_commit() { asm volatile("cp.async.commit_group;"); }
__device__ __forceinline__ void ldm_x4(unsigned& r0, unsigned& r1, unsigned& r2, unsigned& r3,
                                       uint32_t addr) {
    asm volatile("ldmatrix.sync.aligned.m8n8.x4.shared.b16 {%0,%1,%2,%3}, [%4];"
                 : "=r"(r0), "=r"(r1), "=r"(r2), "=r"(r3) : "r"(addr));
}

// ---------------- weight fp32 -> fp16 (layers 2-5, one launch) ---------------
struct WPtrs { const float* w[8]; };
__global__ void wconv_kernel(WPtrs p, __half* __restrict__ o) {
    int which = blockIdx.y;
    int i = blockIdx.x * 256 + threadIdx.x;
    if (i < 40000) o[(size_t)which * 40000 + i] = __float2half(p.w[which][i]);
}

__global__ void wconv1_kernel(const float* __restrict__ Wl, const float* __restrict__ Wr,
                              __half* __restrict__ o) {
    int i = blockIdx.x * 256 + threadIdx.x;
    if (i >= 2 * 200 * 16) return;
    int which = i / 3200, idx = i % 3200;
    int r = idx / 16, c = idx % 16;
    const float* W = which ? Wr : Wl;
    o[i] = __float2half(c < 11 ? W[r * 11 + c] : 0.f);
}

__global__ void xpad_kernel(const float* __restrict__ x, __half* __restrict__ xh, int n) {
    int i = blockIdx.x * 256 + threadIdx.x;
    if (i >= n) return;
    __half v[16];
#pragma unroll
    for (int c = 0; c < 11; c++) v[c] = __float2half(x[(size_t)i * 11 + c]);
#pragma unroll
    for (int c = 11; c < 16; c++) v[c] = __float2half(0.f);
    *(uint4*)(xh + (size_t)i * 16)     = *(uint4*)v;
    *(uint4*)(xh + (size_t)i * 16 + 8) = *(uint4*)(v + 8);
}

// ---------------- CSR build -------------------------------------------------
__global__ void count_kernel(const int* __restrict__ dst, int* __restrict__ cnt, int E) {
    int e = blockIdx.x * blockDim.x + threadIdx.x;
    if (e < E) atomicAdd(&cnt[dst[e]], 1);
}

__global__ void gcount_kernel(const int* __restrict__ batch, int* __restrict__ gcnt, int n) {
    int i = blockIdx.x * blockDim.x + threadIdx.x;
    if (i < n) atomicAdd(&gcnt[batch[i]], 1);
}

__global__ void __launch_bounds__(1024) blockscan_kernel(
    const int* __restrict__ cnt, int* __restrict__ rowptr, int* __restrict__ bsum, int n)
{
    __shared__ int sh[1024];
    int tid = threadIdx.x;
    int i = blockIdx.x * 1024 + tid;
    int v = (i < n) ? cnt[i] : 0;
    sh[tid] = v;
    __syncthreads();
    for (int off = 1; off < 1024; off <<= 1) {
        int t = (tid >= off) ? sh[tid - off] : 0;
        __syncthreads();
        sh[tid] += t;
        __syncthreads();
    }
    if (i < n) rowptr[i + 1] = sh[tid];
    if (tid == 1023) bsum[blockIdx.x] = sh[1023];
}

__global__ void bsumscan_kernel(const int* __restrict__ bsum, int* __restrict__ boff, int nb) {
    __shared__ int sh[128];
    int tid = threadIdx.x;
    int v = (tid < nb) ? bsum[tid] : 0;
    sh[tid] = v;
    __syncthreads();
    for (int off = 1; off < 128; off <<= 1) {
        int t = (tid >= off) ? sh[tid - off] : 0;
        __syncthreads();
        sh[tid] += t;
        __syncthreads();
    }
    if (tid < nb) boff[tid] = sh[tid] - v;
}

__global__ void apply_kernel(const int* __restrict__ cnt, int* __restrict__ rowptr,
                             const int* __restrict__ boff, int* __restrict__ cursor,
                             float* __restrict__ invdeg, int n)
{
    int i = blockIdx.x * blockDim.x + threadIdx.x;
    if (i >= n) return;
    int total = rowptr[i + 1] + boff[i >> 10];
    rowptr[i + 1] = total;
    int c = cnt[i];
    cursor[i] = total - c;
    invdeg[i] = 1.0f / (float)max(c, 1);
    if (i == 0) rowptr[0] = 0;
}

__global__ void fill_kernel(const int* __restrict__ src, const int* __restrict__ dst,
                            int* __restrict__ cursor, int* __restrict__ col, int E) {
    int e = blockIdx.x * blockDim.x + threadIdx.x;
    if (e < E) {
        int d = dst[e];
        int pos = atomicAdd(&cursor[d], 1);
        col[pos] = src[e];
    }
}

__global__ void gscan_kernel(const int* __restrict__ gcnt, int* __restrict__ gstart,
                             float* __restrict__ ginv)
{
    if (threadIdx.x == 0) {
        int s = 0;
        for (int g = 0; g < NG; g++) { gstart[g] = s; s += gcnt[g]; }
        gstart[NG] = s;
    }
    __syncthreads();
    int g = threadIdx.x;
    if (g < NG) ginv[g] = 1.0f / (float)max(gcnt[g], 1);
}

// ---------------- 16-dim gather (layer 1, fp16) ------------------------------
__global__ void __launch_bounds__(256) gather16_kernel(
    const int* __restrict__ rowptr, const int* __restrict__ col,
    const __half* __restrict__ xh, const float* __restrict__ invdeg,
    __half* __restrict__ aggh, int nNodes)
{
    int t = threadIdx.x;
    int n = blockIdx.x * 128 + (t >> 1);
    if (n >= nNodes) return;
    int lane = t & 1;
    int s = rowptr[n], e = rowptr[n + 1];
    float acc[8];
#pragma unroll
    for (int q = 0; q < 8; q++) acc[q] = 0.f;
    for (int j = s; j < e; j++) {
        int c = __ldg(&col[j]);
        uint4 v = *(const uint4*)(xh + (size_t)c * 16 + lane * 8);
        const __half2* p = (const __half2*)&v;
#pragma unroll
        for (int q = 0; q < 4; q++) {
            float2 f = __half22float2(p[q]);
            acc[2 * q]     += f.x;
            acc[2 * q + 1] += f.y;
        }
    }
    float id = invdeg[n];
    __half2 o[4];
#pragma unroll
    for (int q = 0; q < 4; q++)
        o[q] = __floats2half2_rn(acc[2 * q] * id, acc[2 * q + 1] * id);
    *(uint4*)(aggh + (size_t)n * 16 + lane * 8) = *(uint4*)o;
}

// ---------------- layer-1 GEMM: dual-source K=16 fp16 MMA --------------------
#define L1S 24
__global__ void __launch_bounds__(256) layer1_kernel(
    const __half* __restrict__ A0, const __half* __restrict__ A1,
    const __half* __restrict__ W0, const __half* __restrict__ W1,
    const float* __restrict__ bias, __half* __restrict__ C, int M)
{
    const int N = 200;
    __shared__ __half As0[128][L1S], As1[128][L1S];
    __shared__ __half Bs0[64][L1S],  Bs1[64][L1S];

    int tid = threadIdx.x;
    int wid = tid >> 5, lane = tid & 31;
    int wm = wid & 3, wn = wid >> 2;
    int lr = lane >> 2, lc = lane & 3;
    int m0 = blockIdx.x * 128, n0 = blockIdx.y * 64;

    {
        int kq = tid & 1, row = tid >> 1;
        int m = m0 + row;
        uint4 v0 = make_uint4(0,0,0,0), v1 = v0;
        if (m < M) {
            v0 = *(const uint4*)(A0 + (size_t)m * 16 + kq * 8);
            v1 = *(const uint4*)(A1 + (size_t)m * 16 + kq * 8);
        }
        *(uint4*)&As0[row][kq * 8] = v0;
        *(uint4*)&As1[row][kq * 8] = v1;
    }
    {
        int lin = tid;
        int which = lin >> 7;
        int idx = lin & 127;
        int kq = idx & 1, row = idx >> 1;
        int n = n0 + row;
        uint4 v = make_uint4(0,0,0,0);
        const __half* W = which ? W1 : W0;
        if (n < N) v = *(const uint4*)(W + (size_t)n * 16 + kq * 8);
        if (which) *(uint4*)&Bs1[row][kq * 8] = v;
        else       *(uint4*)&Bs0[row][kq * 8] = v;
    }
    __syncthreads();

    float acc[2][4][4];
#pragma unroll
    for (int mt = 0; mt < 2; mt++)
#pragma unroll
        for (int nt = 0; nt < 4; nt++)
#pragma unroll
            for (int q = 0; q < 4; q++) acc[mt][nt][q] = 0.f;

#pragma unroll
    for (int sidx = 0; sidx < 2; sidx++) {
        unsigned a[2][4], b[4][2];
#pragma unroll
        for (int mt = 0; mt < 2; mt++) {
            int r = wm * 32 + mt * 16 + lr;
            const __half (*As)[L1S] = sidx ? As1 : As0;
            a[mt][0] = *(const unsigned*)&As[r][lc * 2];
            a[mt][1] = *(const unsigned*)&As[r + 8][lc * 2];
            a[mt][2] = *(const unsigned*)&As[r][lc * 2 + 8];
            a[mt][3] = *(const unsigned*)&As[r + 8][lc * 2 + 8];
        }
#pragma unroll
        for (int nt = 0; nt < 4; nt++) {
            int n = wn * 32 + nt * 8 + lr;
            const __half (*Bs)[L1S] = sidx ? Bs1 : Bs0;
            b[nt][0] = *(const unsigned*)&Bs[n][lc * 2];
            b[nt][1] = *(const unsigned*)&Bs[n][lc * 2 + 8];
        }
#pragma unroll
        for (int mt = 0; mt < 2; mt++)
#pragma unroll
            for (int nt = 0; nt < 4; nt++) {
                asm volatile(
                    "mma.sync.aligned.m16n8k16.row.col.f32.f16.f16.f32 "
                    "{%0,%1,%2,%3}, {%4,%5,%6,%7}, {%8,%9}, {%0,%1,%2,%3};"
                    : "+f"(acc[mt][nt][0]), "+f"(acc[mt][nt][1]),
                      "+f"(acc[mt][nt][2]), "+f"(acc[mt][nt][3])
                    : "r"(a[mt][0]), "r"(a[mt][1]), "r"(a[mt][2]), "r"(a[mt][3]),
                      "r"(b[nt][0]), "r"(b[nt][1]));
            }
    }

#pragma unroll
    for (int mt = 0; mt < 2; mt++) {
#pragma unroll
        for (int nt = 0; nt < 4; nt++) {
            int r = m0 + wm * 32 + mt * 16 + lr;
            int c = n0 + wn * 32 + nt * 8 + lc * 2;
            if (c < N) {
                float b0 = bias[c], b1 = bias[c + 1 < N ? c + 1 : c];
                if (r < M) {
                    __half2 v = __floats2half2_rn(fmaxf(acc[mt][nt][0] + b0, 0.f),
                                                  fmaxf(acc[mt][nt][1] + b1, 0.f));
                    *(__half2*)(C + (size_t)r * N + c) = v;
                }
                if (r + 8 < M) {
                    __half2 v = __floats2half2_rn(fmaxf(acc[mt][nt][2] + b0, 0.f),
                                                  fmaxf(acc[mt][nt][3] + b1, 0.f));
                    *(__half2*)(C + (size_t)(r + 8) * N + c) = v;
                }
            }
        }
    }
}

// ---- 3-stage pipelined dual GEMM, 512 threads, BM=128 BN=128 + fused pool ----
// grid (782, 3). y<2: 128x128 output tile per W (16 warps: 4M x 4N, warp 32x32).
// y==2: mean-pool of A into pool[:, poff:poff+200].
#define DBS 40
#define GD_SZA (128 * DBS * 2)          // 10240 B per A stage
#define GD_SZB (128 * DBS * 2)          // 10240 B per W stage
#define GD_BOFF (3 * GD_SZA)
#define GD_SMEM (3 * GD_SZA + 3 * 2 * GD_SZB)   // 92160 B
__global__ void __launch_bounds__(512) gemm_dual_kernel(
    const __half* __restrict__ A,
    const __half* __restrict__ W0, const __half* __restrict__ W1,
    const float* __restrict__ bias,
    __half* __restrict__ Z, __half* __restrict__ Y, int M,
    const int* __restrict__ gstart, const float* __restrict__ ginv,
    float* __restrict__ pool, int poff)
{
    const int N = 200, K = 200, NIT = 7;
    int tid = threadIdx.x;

    if (blockIdx.y == 2) {
        int pb = blockIdx.x;
        if (pb >= NG * 3) return;
        int g = pb & 255, chunk = pb >> 8;
        int f = tid;
        if (f >= 200) return;
        int s0 = gstart[g], e0 = gstart[g + 1];
        int len = e0 - s0;
        if (len <= 0) return;
        int per = (len + 2) / 3;
        int s = s0 + chunk * per;
        int e = min(s + per, e0);
        if (s >= e) return;
        float acc = 0.f;
        for (int n = s; n < e; n++) acc += __half2float(A[(size_t)n * 200 + f]);
        atomicAdd(&pool[(size_t)g * 1000 + poff + f], acc * ginv[g]);
        return;
    }

    extern __shared__ __half dynsmem[];
    int wid = tid >> 5, lane = tid & 31;
    int wm = wid & 3;     // 4 warps along M (32 rows each)
    int wn = wid >> 2;    // 4 warps along N (32 cols each)
    int lr = lane >> 2, lc = lane & 3;
    int m0 = blockIdx.x * 128, n0 = blockIdx.y * 128;

    uint32_t sBase = (uint32_t)__cvta_generic_to_shared(dynsmem);

    float accZ[2][4][4], accY[2][4][4];
#pragma unroll
    for (int mt = 0; mt < 2; mt++)
#pragma unroll
        for (int nt = 0; nt < 4; nt++)
#pragma unroll
            for (int q = 0; q < 4; q++) { accZ[mt][nt][q] = 0.f; accY[mt][nt][q] = 0.f; }

    uint32_t offA[2];
#pragma unroll
    for (int mt = 0; mt < 2; mt++)
        offA[mt] = ((wm * 32 + mt * 16 + (lane & 15)) * DBS + (lane >> 4) * 8) * 2;
    uint32_t offB[2];
#pragma unroll
    for (int p = 0; p < 2; p++)
        offB[p] = ((wn * 32 + p * 16 + (lane & 7) + ((lane >> 4) << 3)) * DBS
                   + ((lane >> 3) & 1) * 8) * 2;

    // stage: A 512 chunks (1/thread), W0+W1 512 chunks each (1 each/thread)
    auto stage = [&](int buf, int k0) {
        {
            int kq = tid & 3, row = tid >> 2;        // 0..127
            int m = m0 + row, k = k0 + kq * 8;
            bool ok = (m < M) && (k < K);
            const __half* gp = A + (ok ? ((size_t)m * K + k) : 0);
            cp16(sBase + buf * GD_SZA + (row * DBS + kq * 8) * 2, gp, ok ? 16 : 0);
        }
        {
            int kq = tid & 3, row = tid >> 2;
            int n = n0 + row, k = k0 + kq * 8;
            bool ok = (n < N) && (k < K);
            const __half* gp0 = W0 + (ok ? ((size_t)n * K + k) : 0);
            const __half* gp1 = W1 + (ok ? ((size_t)n * K + k) : 0);
            uint32_t bb = sBase + GD_BOFF + buf * 2 * GD_SZB;
            cp16(bb + (row * DBS + kq * 8) * 2, gp0, ok ? 16 : 0);
            cp16(bb + GD_SZB + (row * DBS + kq * 8) * 2, gp1, ok ? 16 : 0);
        }
        cp_commit();
    };

    stage(0, 0);
    stage(1, 32);

    for (int it = 0; it < NIT; it++) {
        if (it + 1 < NIT) asm volatile("cp.async.wait_group 1;");
        else              asm volatile("cp.async.wait_group 0;");
        __syncthreads();
        if (it + 2 < NIT) stage((it + 2) % 3, (it + 2) * 32);

        int buf = it % 3;
        uint32_t aBase = sBase + buf * GD_SZA;
        uint32_t bBase0 = sBase + GD_BOFF + buf * 2 * GD_SZB;
        uint32_t bBase1 = bBase0 + GD_SZB;

#pragma unroll
        for (int ks = 0; ks < 2; ks++) {
            int koB = ks * 32;
            unsigned a[2][4], bZ[4][2], bY[4][2];
#pragma unroll
            for (int mt = 0; mt < 2; mt++)
                ldm_x4(a[mt][0], a[mt][1], a[mt][2], a[mt][3], aBase + offA[mt] + koB);
#pragma unroll
            for (int p = 0; p < 2; p++) {
                ldm_x4(bZ[2*p][0], bZ[2*p][1], bZ[2*p+1][0], bZ[2*p+1][1],
                       bBase0 + offB[p] + koB);
                ldm_x4(bY[2*p][0], bY[2*p][1], bY[2*p+1][0], bY[2*p+1][1],
                       bBase1 + offB[p] + koB);
            }
#pragma unroll
            for (int mt = 0; mt < 2; mt++)
#pragma unroll
                for (int nt = 0; nt < 4; nt++) {
                    asm volatile(
                        "mma.sync.aligned.m16n8k16.row.col.f32.f16.f16.f32 "
                        "{%0,%1,%2,%3}, {%4,%5,%6,%7}, {%8,%9}, {%0,%1,%2,%3};"
                        : "+f"(accZ[mt][nt][0]), "+f"(accZ[mt][nt][1]),
                          "+f"(accZ[mt][nt][2]), "+f"(accZ[mt][nt][3])
                        : "r"(a[mt][0]), "r"(a[mt][1]), "r"(a[mt][2]), "r"(a[mt][3]),
                          "r"(bZ[nt][0]), "r"(bZ[nt][1]));
                    asm volatile(
                        "mma.sync.aligned.m16n8k16.row.col.f32.f16.f16.f32 "
                        "{%0,%1,%2,%3}, {%4,%5,%6,%7}, {%8,%9}, {%0,%1,%2,%3};"
                        : "+f"(accY[mt][nt][0]), "+f"(accY[mt][nt][1]),
                          "+f"(accY[mt][nt][2]), "+f"(accY[mt][nt][3])
                        : "r"(a[mt][0]), "r"(a[mt][1]), "r"(a[mt][2]), "r"(a[mt][3]),
                          "r"(bY[nt][0]), "r"(bY[nt][1]));
                }
        }
    }

#pragma unroll
    for (int mt = 0; mt < 2; mt++) {
#pragma unroll
        for (int nt = 0; nt < 4; nt++) {
            int r = m0 + wm * 32 + mt * 16 + lr;
            int c = n0 + wn * 32 + nt * 8 + lc * 2;
            if (c < N) {
                float b0 = bias[c], b1 = bias[c + 1 < N ? c + 1 : c];
                if (r < M) {
                    *(__half2*)(Z + (size_t)r * N + c) =
                        __floats2half2_rn(accZ[mt][nt][0], accZ[mt][nt][1]);
                    *(__half2*)(Y + (size_t)r * N + c) =
                        __floats2half2_rn(accY[mt][nt][0] + b0, accY[mt][nt][1] + b1);
                }
                if (r + 8 < M) {
                    *(__half2*)(Z + (size_t)(r + 8) * N + c) =
                        __floats2half2_rn(accZ[mt][nt][2], accZ[mt][nt][3]);
                    *(__half2*)(Y + (size_t)(r + 8) * N + c) =
                        __floats2half2_rn(accY[mt][nt][2] + b0, accY[mt][nt][3] + b1);
                }
            }
        }
    }
}

// ---------------- gather + combine: hout = relu(mean(z[nbrs]) + y) ----------
__global__ void __launch_bounds__(256) gather_combine_kernel(
    const int* __restrict__ rowptr, const int* __restrict__ col,
    const __half* __restrict__ z, const __half* __restrict__ y,
    const float* __restrict__ invdeg, __half* __restrict__ hout, int nNodes)
{
    int t = threadIdx.x;
    if (t >= 250) return;
    int n = blockIdx.x * 10 + t / 25;
    if (n >= nNodes) return;
    int lane = t % 25;
    int s = rowptr[n], e = rowptr[n + 1];
    float acc[8];
#pragma unroll
    for (int q = 0; q < 8; q++) acc[q] = 0.f;
    int j = s;
    for (; j + 3 < e; j += 4) {
        int c0 = __ldg(&col[j]);
        int c1 = __ldg(&col[j + 1]);
        int c2 = __ldg(&col[j + 2]);
        int c3 = __ldg(&col[j + 3]);
        uint4 v0 = *(const uint4*)(z + (size_t)c0 * 200 + lane * 8);
        uint4 v1 = *(const uint4*)(z + (size_t)c1 * 200 + lane * 8);
        uint4 v2 = *(const uint4*)(z + (size_t)c2 * 200 + lane * 8);
        uint4 v3 = *(const uint4*)(z + (size_t)c3 * 200 + lane * 8);
        const __half2* p0 = (const __half2*)&v0;
        const __half2* p1 = (const __half2*)&v1;
        const __half2* p2 = (const __half2*)&v2;
        const __half2* p3 = (const __half2*)&v3;
#pragma unroll
        for (int q = 0; q < 4; q++) {
            float2 f0 = __half22float2(p0[q]);
            float2 f1 = __half22float2(p1[q]);
            float2 f2 = __half22float2(p2[q]);
            float2 f3 = __half22float2(p3[q]);
            acc[2 * q]     += (f0.x + f1.x) + (f2.x + f3.x);
            acc[2 * q + 1] += (f0.y + f1.y) + (f2.y + f3.y);
        }
    }
    for (; j < e; j++) {
        int c0 = __ldg(&col[j]);
        uint4 v0 = *(const uint4*)(z + (size_t)c0 * 200 + lane * 8);
        const __half2* p0 = (const __half2*)&v0;
#pragma unroll
        for (int q = 0; q < 4; q++) {
            float2 f0 = __half22float2(p0[q]);
            acc[2 * q]     += f0.x;
            acc[2 * q + 1] += f0.y;
        }
    }
    float id = invdeg[n];
    uint4 yv = *(const uint4*)(y + (size_t)n * 200 + lane * 8);
    const __half2* yp = (const __half2*)&yv;
    __half2 o[4];
#pragma unroll
    for (int q = 0; q < 4; q++) {
        float2 fy = __half22float2(yp[q]);
        o[q] = __floats2half2_rn(fmaxf(acc[2 * q] * id + fy.x, 0.f),
                                 fmaxf(acc[2 * q + 1] * id + fy.y, 0.f));
    }
    *(uint4*)(hout + (size_t)n * 200 + lane * 8) = *(uint4*)o;
}

// ---------------- tf32 GEMM (projection head) --------------------------------
__device__ __forceinline__ unsigned f2tf(float f) {
    unsigned u;
    asm("cvt.rna.tf32.f32 %0, %1;" : "=r"(u) : "f"(f));
    return u;
}

__global__ void __launch_bounds__(256) gemm_tf32_kernel(
    const float* __restrict__ A0, const float* __restrict__ W0,
    const float* __restrict__ bias, float* __restrict__ C,
    int M, int N, int K)
{
    __shared__ unsigned As[128][36];
    __shared__ unsigned Bs[64][36];

    int tid = threadIdx.x;
    int wid = tid >> 5, lane = tid & 31;
    int wm = wid & 3, wn = wid >> 2;
    int lr = lane >> 2, lc = lane & 3;
    int m0 = blockIdx.x * 128, n0 = blockIdx.y * 64;

    float acc[2][4][4];
#pragma unroll
    for (int mt = 0; mt < 2; mt++)
#pragma unroll
        for (int nt = 0; nt < 4; nt++)
#pragma unroll
            for (int q = 0; q < 4; q++) acc[mt][nt][q] = 0.f;

    for (int k0 = 0; k0 < K; k0 += 32) {
#pragma unroll
        for (int i = 0; i < 16; i++) {
            int lin = tid + i * 256;
            int kk = lin & 31, row = lin >> 5;
            int m = m0 + row, k = k0 + kk;
            float v = (m < M && k < K) ? A0[(size_t)m * K + k] : 0.f;
            As[row][kk] = f2tf(v);
        }
#pragma unroll
        for (int i = 0; i < 8; i++) {
            int lin = tid + i * 256;
            int kk = lin & 31, row = lin >> 5;
            int n = n0 + row, k = k0 + kk;
            float v = (n < N && k < K) ? W0[(size_t)n * K + k] : 0.f;
            Bs[row][kk] = f2tf(v);
        }
        __syncthreads();

#pragma unroll
        for (int ks = 0; ks < 4; ks++) {
            unsigned a[2][4], b[4][2];
#pragma unroll
            for (int mt = 0; mt < 2; mt++) {
                int r = wm * 32 + mt * 16 + lr;
                a[mt][0] = As[r][ks * 8 + lc];
                a[mt][1] = As[r + 8][ks * 8 + lc];
                a[mt][2] = As[r][ks * 8 + lc + 4];
                a[mt][3] = As[r + 8][ks * 8 + lc + 4];
            }
#pragma unroll
            for (int nt = 0; nt < 4; nt++) {
                int n = wn * 32 + nt * 8 + lr;
                b[nt][0] = Bs[n][ks * 8 + lc];
                b[nt][1] = Bs[n][ks * 8 + lc + 4];
            }
#pragma unroll
            for (int mt = 0; mt < 2; mt++)
#pragma unroll
                for (int nt = 0; nt < 4; nt++) {
                    asm volatile(
                        "mma.sync.aligned.m16n8k8.row.col.f32.tf32.tf32.f32 "
                        "{%0,%1,%2,%3}, {%4,%5,%6,%7}, {%8,%9}, {%0,%1,%2,%3};"
                        : "+f"(acc[mt][nt][0]), "+f"(acc[mt][nt][1]),
                          "+f"(acc[mt][nt][2]), "+f"(acc[mt][nt][3])
                        : "r"(a[mt][0]), "r"(a[mt][1]), "r"(a[mt][2]), "r"(a[mt][3]),
                          "r"(b[nt][0]), "r"(b[nt][1]));
                }
        }
        __syncthreads();
    }

#pragma unroll
    for (int mt = 0; mt < 2; mt++) {
#pragma unroll
        for (int nt = 0; nt < 4; nt++) {
            int r = m0 + wm * 32 + mt * 16 + lr;
            int c = n0 + wn * 32 + nt * 8 + lc * 2;
#pragma unroll
            for (int q = 0; q < 4; q++) {
                int rr = r + (q >> 1) * 8;
                int cc = c + (q & 1);
                if (rr < M && cc < N)
                    C[(size_t)rr * N + cc] = acc[mt][nt][q] + bias[cc];
            }
        }
    }
}

// ---------------- standalone graph mean-pool (final layer) -------------------
__global__ void pool_kernel(const __half* __restrict__ h, const int* __restrict__ gstart,
                            const float* __restrict__ ginv, float* __restrict__ pool, int off)
{
    int g = blockIdx.x;
    int chunk = blockIdx.y;
    int f = threadIdx.x;
    if (f >= 200) return;
    int s0 = gstart[g], e0 = gstart[g + 1];
    int len = e0 - s0;
    if (len <= 0) return;
    int per = (len + 7) / 8;
    int s = s0 + chunk * per;
    int e = min(s + per, e0);
    if (s >= e) return;
    float acc = 0.f;
    for (int n = s; n < e; n++) acc += __half2float(h[(size_t)n * 200 + f]);
    atomicAdd(&pool[(size_t)g * 1000 + off + f], acc * ginv[g]);
}

// ---------------- final 250 -> 1 + sigmoid ----------------------------------
__global__ void mlp3_kernel(const float* __restrict__ in, const float* __restrict__ w,
                            const float* __restrict__ b, float* __restrict__ out)
{
    int g = threadIdx.x;
    float acc = b[0];
    for (int k = 0; k < 250; k++) acc += in[g * 250 + k] * w[k];
    out[g] = 1.0f / (1.0f + expf(-acc));
}

// ---------------- launch ----------------------------------------------------
extern "C" void kernel_launch(void* const* d_in, const int* in_sizes, int n_in,
                              void* d_out, int out_size)
{
    const float* x     = (const float*)d_in[0];
    const int*   ei    = (const int*)d_in[1];
    const int*   batch = (const int*)d_in[2];
    const float* Wl[5], *bl[5], *Wr[5];
    for (int i = 0; i < 5; i++) {
        Wl[i] = (const float*)d_in[3 + 3 * i];
        bl[i] = (const float*)d_in[4 + 3 * i];
        Wr[i] = (const float*)d_in[5 + 3 * i];
    }
    const float* pw1 = (const float*)d_in[18];
    const float* pb1 = (const float*)d_in[19];
    const float* pw2 = (const float*)d_in[20];
    const float* pb2 = (const float*)d_in[21];
    const float* pw3 = (const float*)d_in[22];
    const float* pb3 = (const float*)d_in[23];
    float* out = (float*)d_out;

    int E = in_sizes[1] / 2;
    const int* src = ei;
    const int* dst = ei + E;

    __half *hA, *hB, *zb, *yb, *xh, *aggh, *w16, *w1;
    float *invdeg, *pool, *m1, *m2, *ginv;
    int *gstart, *gcnt, *rowcnt, *rowptr, *cursor, *col, *bsum, *boff;
    cudaGetSymbolAddress((void**)&hA, g_hA);
    cudaGetSymbolAddress((void**)&hB, g_hB);
    cudaGetSymbolAddress((void**)&zb, g_z);
    cudaGetSymbolAddress((void**)&yb, g_y);
    cudaGetSymbolAddress((void**)&xh, g_xh);
    cudaGetSymbolAddress((void**)&aggh, g_aggh);
    cudaGetSymbolAddress((void**)&w16, g_w16);
    cudaGetSymbolAddress((void**)&w1, g_w1);
    cudaGetSymbolAddress((void**)&invdeg, g_invdeg);
    cudaGetSymbolAddress((void**)&pool, g_pool);
    cudaGetSymbolAddress((void**)&m1, g_m1);
    cudaGetSymbolAddress((void**)&m2, g_m2);
    cudaGetSymbolAddress((void**)&gstart, g_gstart);
    cudaGetSymbolAddress((void**)&gcnt, g_gcnt);
    cudaGetSymbolAddress((void**)&ginv, g_ginv);
    cudaGetSymbolAddress((void**)&rowcnt, g_rowcnt);
    cudaGetSymbolAddress((void**)&rowptr, g_rowptr);
    cudaGetSymbolAddress((void**)&cursor, g_cursor);
    cudaGetSymbolAddress((void**)&col, g_col);
    cudaGetSymbolAddress((void**)&bsum, g_bsum);
    cudaGetSymbolAddress((void**)&boff, g_boff);

    cudaMemsetAsync(rowcnt, 0, NN * sizeof(int));
    cudaMemsetAsync(gcnt, 0, NG * sizeof(int));
    cudaMemsetAsync(pool, 0, NG * 1000 * sizeof(float));

    // weight conversions + x padding
    {
        WPtrs p;
        for (int L = 1; L < 5; L++) {
            p.w[2 * (L - 1)]     = Wl[L];
            p.w[2 * (L - 1) + 1] = Wr[L];
        }
        dim3 wg((40000 + 255) / 256, 8);
        wconv_kernel<<<wg, 256>>>(p, w16);
        wconv1_kernel<<<(2 * 200 * 16 + 255) / 256, 256>>>(Wl[0], Wr[0], w1);
        xpad_kernel<<<(NN + 255) / 256, 256>>>(x, xh, NN);
    }

    // CSR build (by dst) + invdeg + graph segments
    count_kernel<<<(E + 255) / 256, 256>>>(dst, rowcnt, E);
    gcount_kernel<<<(NN + 255) / 256, 256>>>(batch, gcnt, NN);
    blockscan_kernel<<<NB_SCAN, 1024>>>(rowcnt, rowptr, bsum, NN);
    bsumscan_kernel<<<1, 128>>>(bsum, boff, NB_SCAN);
    apply_kernel<<<(NN + 255) / 256, 256>>>(rowcnt, rowptr, boff, cursor, invdeg, NN);
    fill_kernel<<<(E + 255) / 256, 256>>>(src, dst, cursor, col, E);
    gscan_kernel<<<1, 256>>>(gcnt, gstart, ginv);

    // ---- layer 1 (fp16 path, K=16) ----
    gather16_kernel<<<(NN + 127) / 128, 256>>>(rowptr, col, xh, invdeg, aggh, NN);
    {
        dim3 grid((NN + 127) / 128, 4);
        layer1_kernel<<<grid, 256>>>(aggh, xh, w1, w1 + 3200, bl[0], hA, NN);
    }

    // ---- layers 2-5: dual GEMM BN=128 (+ fused pool) -> gather+combine ----
    cudaFuncSetAttribute(gemm_dual_kernel,
                         cudaFuncAttributeMaxDynamicSharedMemorySize, GD_SMEM);
    const __half* hin = hA;
    __half* hout = hB;
    for (int L = 1; L < 5; L++) {
        const __half* wl = w16 + (size_t)(L - 1) * 80000;
        const __half* wr = wl + 40000;
        dim3 grid((NN + 127) / 128, 3);
        gemm_dual_kernel<<<grid, 512, GD_SMEM>>>(hin, wl, wr, bl[L], zb, yb, NN,
                                                 gstart, ginv, pool, (L - 1) * 200);
        gather_combine_kernel<<<(NN + 9) / 10, 256>>>(rowptr, col, zb, yb, invdeg, hout, NN);
        const __half* t = hin;
        hin = hout;
        hout = (__half*)t;
    }
    // final layer's pool
    {
        dim3 pgrid(NG, 8);
        pool_kernel<<<pgrid, 256>>>(hin, gstart, ginv, pool, 800);
    }

    // ---- projection head (fp32/tf32) ----
    {
        dim3 g1((NG + 127) / 128, (500 + 63) / 64);
        gemm_tf32_kernel<<<g1, 256>>>(pool, pw1, pb1, m1, NG, 500, 1000);
        dim3 g2((NG + 127) / 128, (250 + 63) / 64);
        gemm_tf32_kernel<<<g2, 256>>>(m1, pw2, pb2, m2, NG, 250, 500);
        mlp3_kernel<<<1, 256>>>(m2, pw3, pb3, out);
    }
}

// round 16
// speedup vs baseline: 1.0808x; 1.0808x over previous
#include <cuda_runtime.h>
#include <cuda_fp16.h>
#include <stdint.h>
#include <math.h>

#define NN 100000
#define NG 256
#define MAXE 3400000
#define NB_SCAN ((NN + 1023) / 1024)

// ---------------- scratch (device globals; no allocations allowed) ----------
__device__ __half g_hA[(size_t)NN * 200];
__device__ __half g_hB[(size_t)NN * 200];
__device__ __half g_z [(size_t)NN * 200];
__device__ __half g_y [(size_t)NN * 200];
__device__ __half g_xh[(size_t)NN * 16];
__device__ __half g_aggh[(size_t)NN * 16];
__device__ __half g_w16[8 * 200 * 200];
__device__ __half g_w1[2 * 200 * 16];
__device__ float g_invdeg[NN];
__device__ float g_pool[NG * 1000];
__device__ float g_m1[NG * 500];
__device__ float g_m2[NG * 250];
__device__ int   g_gstart[NG + 1];
__device__ int   g_gcnt[NG];
__device__ float g_ginv[NG];
__device__ int   g_rowcnt[NN];
__device__ int   g_rowptr[NN + 1];
__device__ int   g_cursor[NN];
__device__ int   g_col[MAXE];
__device__ int   g_bsum[NB_SCAN];
__device__ int   g_boff[NB_SCAN];

// ---------------- small helpers ----------------------------------------------
__device__ __forceinline__ void cp16(uint32_t saddr, const void* gaddr, int sz) {
    asm volatile("cp.async.cg.shared.global [%0], [%1], 16, %2;"
                 :: "r"(saddr), "l"(gaddr), "r"(sz));
}
__device__ __forceinline__ void cp_commit() { asm volatile("cp.async.commit_group;"); }
__device__ __forceinline__ void ldm_x4(unsigned& r0, unsigned& r1, unsigned& r2, unsigned& r3,
                                       uint32_t addr) {
    asm volatile("ldmatrix.sync.aligned.m8n8.x4.shared.b16 {%0,%1,%2,%3}, [%4];"
                 : "=r"(r0), "=r"(r1), "=r"(r2), "=r"(r3) : "r"(addr));
}

// ---------------- weight fp32 -> fp16 (layers 2-5, one launch) ---------------
struct WPtrs { const float* w[8]; };
__global__ void wconv_kernel(WPtrs p, __half* __restrict__ o) {
    int which = blockIdx.y;
    int i = blockIdx.x * 256 + threadIdx.x;
    if (i < 40000) o[(size_t)which * 40000 + i] = __float2half(p.w[which][i]);
}

__global__ void wconv1_kernel(const float* __restrict__ Wl, const float* __restrict__ Wr,
                              __half* __restrict__ o) {
    int i = blockIdx.x * 256 + threadIdx.x;
    if (i >= 2 * 200 * 16) return;
    int which = i / 3200, idx = i % 3200;
    int r = idx / 16, c = idx % 16;
    const float* W = which ? Wr : Wl;
    o[i] = __float2half(c < 11 ? W[r * 11 + c] : 0.f);
}

__global__ void xpad_kernel(const float* __restrict__ x, __half* __restrict__ xh, int n) {
    int i = blockIdx.x * 256 + threadIdx.x;
    if (i >= n) return;
    __half v[16];
#pragma unroll
    for (int c = 0; c < 11; c++) v[c] = __float2half(x[(size_t)i * 11 + c]);
#pragma unroll
    for (int c = 11; c < 16; c++) v[c] = __float2half(0.f);
    *(uint4*)(xh + (size_t)i * 16)     = *(uint4*)v;
    *(uint4*)(xh + (size_t)i * 16 + 8) = *(uint4*)(v + 8);
}

// ---------------- CSR build -------------------------------------------------
__global__ void count_kernel(const int* __restrict__ dst, int* __restrict__ cnt, int E) {
    int e = blockIdx.x * blockDim.x + threadIdx.x;
    if (e < E) atomicAdd(&cnt[dst[e]], 1);
}

__global__ void gcount_kernel(const int* __restrict__ batch, int* __restrict__ gcnt, int n) {
    int i = blockIdx.x * blockDim.x + threadIdx.x;
    if (i < n) atomicAdd(&gcnt[batch[i]], 1);
}

__global__ void __launch_bounds__(1024) blockscan_kernel(
    const int* __restrict__ cnt, int* __restrict__ rowptr, int* __restrict__ bsum, int n)
{
    __shared__ int sh[1024];
    int tid = threadIdx.x;
    int i = blockIdx.x * 1024 + tid;
    int v = (i < n) ? cnt[i] : 0;
    sh[tid] = v;
    __syncthreads();
    for (int off = 1; off < 1024; off <<= 1) {
        int t = (tid >= off) ? sh[tid - off] : 0;
        __syncthreads();
        sh[tid] += t;
        __syncthreads();
    }
    if (i < n) rowptr[i + 1] = sh[tid];
    if (tid == 1023) bsum[blockIdx.x] = sh[1023];
}

__global__ void bsumscan_kernel(const int* __restrict__ bsum, int* __restrict__ boff, int nb) {
    __shared__ int sh[128];
    int tid = threadIdx.x;
    int v = (tid < nb) ? bsum[tid] : 0;
    sh[tid] = v;
    __syncthreads();
    for (int off = 1; off < 128; off <<= 1) {
        int t = (tid >= off) ? sh[tid - off] : 0;
        __syncthreads();
        sh[tid] += t;
        __syncthreads();
    }
    if (tid < nb) boff[tid] = sh[tid] - v;
}

__global__ void apply_kernel(const int* __restrict__ cnt, int* __restrict__ rowptr,
                             const int* __restrict__ boff, int* __restrict__ cursor,
                             float* __restrict__ invdeg, int n)
{
    int i = blockIdx.x * blockDim.x + threadIdx.x;
    if (i >= n) return;
    int total = rowptr[i + 1] + boff[i >> 10];
    rowptr[i + 1] = total;
    int c = cnt[i];
    cursor[i] = total - c;
    invdeg[i] = 1.0f / (float)max(c, 1);
    if (i == 0) rowptr[0] = 0;
}

__global__ void fill_kernel(const int* __restrict__ src, const int* __restrict__ dst,
                            int* __restrict__ cursor, int* __restrict__ col, int E) {
    int e = blockIdx.x * blockDim.x + threadIdx.x;
    if (e < E) {
        int d = dst[e];
        int pos = atomicAdd(&cursor[d], 1);
        col[pos] = src[e];
    }
}

__global__ void gscan_kernel(const int* __restrict__ gcnt, int* __restrict__ gstart,
                             float* __restrict__ ginv)
{
    if (threadIdx.x == 0) {
        int s = 0;
        for (int g = 0; g < NG; g++) { gstart[g] = s; s += gcnt[g]; }
        gstart[NG] = s;
    }
    __syncthreads();
    int g = threadIdx.x;
    if (g < NG) ginv[g] = 1.0f / (float)max(gcnt[g], 1);
}

// ---------------- 16-dim gather (layer 1, fp16) ------------------------------
__global__ void __launch_bounds__(256) gather16_kernel(
    const int* __restrict__ rowptr, const int* __restrict__ col,
    const __half* __restrict__ xh, const float* __restrict__ invdeg,
    __half* __restrict__ aggh, int nNodes)
{
    int t = threadIdx.x;
    int n = blockIdx.x * 128 + (t >> 1);
    if (n >= nNodes) return;
    int lane = t & 1;
    int s = rowptr[n], e = rowptr[n + 1];
    float acc[8];
#pragma unroll
    for (int q = 0; q < 8; q++) acc[q] = 0.f;
    for (int j = s; j < e; j++) {
        int c = __ldg(&col[j]);
        uint4 v = *(const uint4*)(xh + (size_t)c * 16 + lane * 8);
        const __half2* p = (const __half2*)&v;
#pragma unroll
        for (int q = 0; q < 4; q++) {
            float2 f = __half22float2(p[q]);
            acc[2 * q]     += f.x;
            acc[2 * q + 1] += f.y;
        }
    }
    float id = invdeg[n];
    __half2 o[4];
#pragma unroll
    for (int q = 0; q < 4; q++)
        o[q] = __floats2half2_rn(acc[2 * q] * id, acc[2 * q + 1] * id);
    *(uint4*)(aggh + (size_t)n * 16 + lane * 8) = *(uint4*)o;
}

// ---------------- layer-1 GEMM: dual-source K=16 fp16 MMA --------------------
#define L1S 24
__global__ void __launch_bounds__(256) layer1_kernel(
    const __half* __restrict__ A0, const __half* __restrict__ A1,
    const __half* __restrict__ W0, const __half* __restrict__ W1,
    const float* __restrict__ bias, __half* __restrict__ C, int M)
{
    const int N = 200;
    __shared__ __half As0[128][L1S], As1[128][L1S];
    __shared__ __half Bs0[64][L1S],  Bs1[64][L1S];

    int tid = threadIdx.x;
    int wid = tid >> 5, lane = tid & 31;
    int wm = wid & 3, wn = wid >> 2;
    int lr = lane >> 2, lc = lane & 3;
    int m0 = blockIdx.x * 128, n0 = blockIdx.y * 64;

    {
        int kq = tid & 1, row = tid >> 1;
        int m = m0 + row;
        uint4 v0 = make_uint4(0,0,0,0), v1 = v0;
        if (m < M) {
            v0 = *(const uint4*)(A0 + (size_t)m * 16 + kq * 8);
            v1 = *(const uint4*)(A1 + (size_t)m * 16 + kq * 8);
        }
        *(uint4*)&As0[row][kq * 8] = v0;
        *(uint4*)&As1[row][kq * 8] = v1;
    }
    {
        int lin = tid;
        int which = lin >> 7;
        int idx = lin & 127;
        int kq = idx & 1, row = idx >> 1;
        int n = n0 + row;
        uint4 v = make_uint4(0,0,0,0);
        const __half* W = which ? W1 : W0;
        if (n < N) v = *(const uint4*)(W + (size_t)n * 16 + kq * 8);
        if (which) *(uint4*)&Bs1[row][kq * 8] = v;
        else       *(uint4*)&Bs0[row][kq * 8] = v;
    }
    __syncthreads();

    float acc[2][4][4];
#pragma unroll
    for (int mt = 0; mt < 2; mt++)
#pragma unroll
        for (int nt = 0; nt < 4; nt++)
#pragma unroll
            for (int q = 0; q < 4; q++) acc[mt][nt][q] = 0.f;

#pragma unroll
    for (int sidx = 0; sidx < 2; sidx++) {
        unsigned a[2][4], b[4][2];
#pragma unroll
        for (int mt = 0; mt < 2; mt++) {
            int r = wm * 32 + mt * 16 + lr;
            const __half (*As)[L1S] = sidx ? As1 : As0;
            a[mt][0] = *(const unsigned*)&As[r][lc * 2];
            a[mt][1] = *(const unsigned*)&As[r + 8][lc * 2];
            a[mt][2] = *(const unsigned*)&As[r][lc * 2 + 8];
            a[mt][3] = *(const unsigned*)&As[r + 8][lc * 2 + 8];
        }
#pragma unroll
        for (int nt = 0; nt < 4; nt++) {
            int n = wn * 32 + nt * 8 + lr;
            const __half (*Bs)[L1S] = sidx ? Bs1 : Bs0;
            b[nt][0] = *(const unsigned*)&Bs[n][lc * 2];
            b[nt][1] = *(const unsigned*)&Bs[n][lc * 2 + 8];
        }
#pragma unroll
        for (int mt = 0; mt < 2; mt++)
#pragma unroll
            for (int nt = 0; nt < 4; nt++) {
                asm volatile(
                    "mma.sync.aligned.m16n8k16.row.col.f32.f16.f16.f32 "
                    "{%0,%1,%2,%3}, {%4,%5,%6,%7}, {%8,%9}, {%0,%1,%2,%3};"
                    : "+f"(acc[mt][nt][0]), "+f"(acc[mt][nt][1]),
                      "+f"(acc[mt][nt][2]), "+f"(acc[mt][nt][3])
                    : "r"(a[mt][0]), "r"(a[mt][1]), "r"(a[mt][2]), "r"(a[mt][3]),
                      "r"(b[nt][0]), "r"(b[nt][1]));
            }
    }

#pragma unroll
    for (int mt = 0; mt < 2; mt++) {
#pragma unroll
        for (int nt = 0; nt < 4; nt++) {
            int r = m0 + wm * 32 + mt * 16 + lr;
            int c = n0 + wn * 32 + nt * 8 + lc * 2;
            if (c < N) {
                float b0 = bias[c], b1 = bias[c + 1 < N ? c + 1 : c];
                if (r < M) {
                    __half2 v = __floats2half2_rn(fmaxf(acc[mt][nt][0] + b0, 0.f),
                                                  fmaxf(acc[mt][nt][1] + b1, 0.f));
                    *(__half2*)(C + (size_t)r * N + c) = v;
                }
                if (r + 8 < M) {
                    __half2 v = __floats2half2_rn(fmaxf(acc[mt][nt][2] + b0, 0.f),
                                                  fmaxf(acc[mt][nt][3] + b1, 0.f));
                    *(__half2*)(C + (size_t)(r + 8) * N + c) = v;
                }
            }
        }
    }
}

// ---------------- 3-stage pipelined dual-output GEMM + fused pool ------------
#define DBS 40
#define GD_SZA (128 * DBS * 2)
#define GD_SZB (64 * DBS * 2)
#define GD_BOFF (3 * GD_SZA)
#define GD_SMEM (3 * GD_SZA + 3 * 2 * GD_SZB)
__global__ void __launch_bounds__(256) gemm_dual_kernel(
    const __half* __restrict__ A,
    const __half* __restrict__ W0, const __half* __restrict__ W1,
    const float* __restrict__ bias,
    __half* __restrict__ Z, __half* __restrict__ Y, int M,
    const int* __restrict__ gstart, const float* __restrict__ ginv,
    float* __restrict__ pool, int poff)
{
    const int N = 200, K = 200, NIT = 7;
    int tid = threadIdx.x;

    if (blockIdx.y == 4) {
        int pb = blockIdx.x;
        if (pb >= NG * 3) return;
        int g = pb & 255, chunk = pb >> 8;
        int f = tid;
        if (f >= 200) return;
        int s0 = gstart[g], e0 = gstart[g + 1];
        int len = e0 - s0;
        if (len <= 0) return;
        int per = (len + 2) / 3;
        int s = s0 + chunk * per;
        int e = min(s + per, e0);
        if (s >= e) return;
        float acc = 0.f;
        for (int n = s; n < e; n++) acc += __half2float(A[(size_t)n * 200 + f]);
        atomicAdd(&pool[(size_t)g * 1000 + poff + f], acc * ginv[g]);
        return;
    }

    extern __shared__ __half dynsmem[];
    int wid = tid >> 5, lane = tid & 31;
    int wm = wid & 3, wn = wid >> 2;
    int lr = lane >> 2, lc = lane & 3;
    int m0 = blockIdx.x * 128, n0 = blockIdx.y * 64;

    uint32_t sBase = (uint32_t)__cvta_generic_to_shared(dynsmem);

    float accZ[2][4][4], accY[2][4][4];
#pragma unroll
    for (int mt = 0; mt < 2; mt++)
#pragma unroll
        for (int nt = 0; nt < 4; nt++)
#pragma unroll
            for (int q = 0; q < 4; q++) { accZ[mt][nt][q] = 0.f; accY[mt][nt][q] = 0.f; }

    uint32_t offA[2];
#pragma unroll
    for (int mt = 0; mt < 2; mt++)
        offA[mt] = ((wm * 32 + mt * 16 + (lane & 15)) * DBS + (lane >> 4) * 8) * 2;
    uint32_t offB[2];
#pragma unroll
    for (int p = 0; p < 2; p++)
        offB[p] = ((wn * 32 + p * 16 + (lane & 7) + ((lane >> 4) << 3)) * DBS
                   + ((lane >> 3) & 1) * 8) * 2;

    auto stage = [&](int buf, int k0) {
#pragma unroll
        for (int i = 0; i < 2; i++) {
            int lin = tid + i * 256;
            int kq = lin & 3, row = lin >> 2;
            int m = m0 + row, k = k0 + kq * 8;
            bool ok = (m < M) && (k < K);
            const __half* gp = A + (ok ? ((size_t)m * K + k) : 0);
            cp16(sBase + buf * GD_SZA + (row * DBS + kq * 8) * 2, gp, ok ? 16 : 0);
        }
        {
            int kq = tid & 3, row = tid >> 2;
            int n = n0 + row, k = k0 + kq * 8;
            bool ok = (n < N) && (k < K);
            const __half* gp0 = W0 + (ok ? ((size_t)n * K + k) : 0);
            const __half* gp1 = W1 + (ok ? ((size_t)n * K + k) : 0);
            uint32_t bb = sBase + GD_BOFF + buf * 2 * GD_SZB;
            cp16(bb + (row * DBS + kq * 8) * 2, gp0, ok ? 16 : 0);
            cp16(bb + GD_SZB + (row * DBS + kq * 8) * 2, gp1, ok ? 16 : 0);
        }
        cp_commit();
    };

    stage(0, 0);
    stage(1, 32);

    for (int it = 0; it < NIT; it++) {
        if (it + 1 < NIT) asm volatile("cp.async.wait_group 1;");
        else              asm volatile("cp.async.wait_group 0;");
        __syncthreads();
        if (it + 2 < NIT) stage((it + 2) % 3, (it + 2) * 32);

        int buf = it % 3;
        uint32_t aBase = sBase + buf * GD_SZA;
        uint32_t bBase0 = sBase + GD_BOFF + buf * 2 * GD_SZB;
        uint32_t bBase1 = bBase0 + GD_SZB;

#pragma unroll
        for (int ks = 0; ks < 2; ks++) {
            int koB = ks * 32;
            unsigned a[2][4], bZ[4][2], bY[4][2];
#pragma unroll
            for (int mt = 0; mt < 2; mt++)
                ldm_x4(a[mt][0], a[mt][1], a[mt][2], a[mt][3], aBase + offA[mt] + koB);
#pragma unroll
            for (int p = 0; p < 2; p++) {
                ldm_x4(bZ[2*p][0], bZ[2*p][1], bZ[2*p+1][0], bZ[2*p+1][1],
                       bBase0 + offB[p] + koB);
                ldm_x4(bY[2*p][0], bY[2*p][1], bY[2*p+1][0], bY[2*p+1][1],
                       bBase1 + offB[p] + koB);
            }
#pragma unroll
            for (int mt = 0; mt < 2; mt++)
#pragma unroll
                for (int nt = 0; nt < 4; nt++) {
                    asm volatile(
                        "mma.sync.aligned.m16n8k16.row.col.f32.f16.f16.f32 "
                        "{%0,%1,%2,%3}, {%4,%5,%6,%7}, {%8,%9}, {%0,%1,%2,%3};"
                        : "+f"(accZ[mt][nt][0]), "+f"(accZ[mt][nt][1]),
                          "+f"(accZ[mt][nt][2]), "+f"(accZ[mt][nt][3])
                        : "r"(a[mt][0]), "r"(a[mt][1]), "r"(a[mt][2]), "r"(a[mt][3]),
                          "r"(bZ[nt][0]), "r"(bZ[nt][1]));
                    asm volatile(
                        "mma.sync.aligned.m16n8k16.row.col.f32.f16.f16.f32 "
                        "{%0,%1,%2,%3}, {%4,%5,%6,%7}, {%8,%9}, {%0,%1,%2,%3};"
                        : "+f"(accY[mt][nt][0]), "+f"(accY[mt][nt][1]),
                          "+f"(accY[mt][nt][2]), "+f"(accY[mt][nt][3])
                        : "r"(a[mt][0]), "r"(a[mt][1]), "r"(a[mt][2]), "r"(a[mt][3]),
                          "r"(bY[nt][0]), "r"(bY[nt][1]));
                }
        }
    }

#pragma unroll
    for (int mt = 0; mt < 2; mt++) {
#pragma unroll
        for (int nt = 0; nt < 4; nt++) {
            int r = m0 + wm * 32 + mt * 16 + lr;
            int c = n0 + wn * 32 + nt * 8 + lc * 2;
            if (c < N) {
                float b0 = bias[c], b1 = bias[c + 1 < N ? c + 1 : c];
                if (r < M) {
                    *(__half2*)(Z + (size_t)r * N + c) =
                        __floats2half2_rn(accZ[mt][nt][0], accZ[mt][nt][1]);
                    *(__half2*)(Y + (size_t)r * N + c) =
                        __floats2half2_rn(accY[mt][nt][0] + b0, accY[mt][nt][1] + b1);
                }
                if (r + 8 < M) {
                    *(__half2*)(Z + (size_t)(r + 8) * N + c) =
                        __floats2half2_rn(accZ[mt][nt][2], accZ[mt][nt][3]);
                    *(__half2*)(Y + (size_t)(r + 8) * N + c) =
                        __floats2half2_rn(accY[mt][nt][2] + b0, accY[mt][nt][3] + b1);
                }
            }
        }
    }
}

// ---------------- gather + combine: hout = relu(mean(z[nbrs]) + y) ----------
__global__ void __launch_bounds__(256) gather_combine_kernel(
    const int* __restrict__ rowptr, const int* __restrict__ col,
    const __half* __restrict__ z, const __half* __restrict__ y,
    const float* __restrict__ invdeg, __half* __restrict__ hout, int nNodes)
{
    int t = threadIdx.x;
    if (t >= 250) return;
    int n = blockIdx.x * 10 + t / 25;
    if (n >= nNodes) return;
    int lane = t % 25;
    int s = rowptr[n], e = rowptr[n + 1];
    float acc[8];
#pragma unroll
    for (int q = 0; q < 8; q++) acc[q] = 0.f;
    int j = s;
    for (; j + 3 < e; j += 4) {
        int c0 = __ldg(&col[j]);
        int c1 = __ldg(&col[j + 1]);
        int c2 = __ldg(&col[j + 2]);
        int c3 = __ldg(&col[j + 3]);
        uint4 v0 = *(const uint4*)(z + (size_t)c0 * 200 + lane * 8);
        uint4 v1 = *(const uint4*)(z + (size_t)c1 * 200 + lane * 8);
        uint4 v2 = *(const uint4*)(z + (size_t)c2 * 200 + lane * 8);
        uint4 v3 = *(const uint4*)(z + (size_t)c3 * 200 + lane * 8);
        const __half2* p0 = (const __half2*)&v0;
        const __half2* p1 = (const __half2*)&v1;
        const __half2* p2 = (const __half2*)&v2;
        const __half2* p3 = (const __half2*)&v3;
#pragma unroll
        for (int q = 0; q < 4; q++) {
            float2 f0 = __half22float2(p0[q]);
            float2 f1 = __half22float2(p1[q]);
            float2 f2 = __half22float2(p2[q]);
            float2 f3 = __half22float2(p3[q]);
            acc[2 * q]     += (f0.x + f1.x) + (f2.x + f3.x);
            acc[2 * q + 1] += (f0.y + f1.y) + (f2.y + f3.y);
        }
    }
    for (; j < e; j++) {
        int c0 = __ldg(&col[j]);
        uint4 v0 = *(const uint4*)(z + (size_t)c0 * 200 + lane * 8);
        const __half2* p0 = (const __half2*)&v0;
#pragma unroll
        for (int q = 0; q < 4; q++) {
            float2 f0 = __half22float2(p0[q]);
            acc[2 * q]     += f0.x;
            acc[2 * q + 1] += f0.y;
        }
    }
    float id = invdeg[n];
    uint4 yv = *(const uint4*)(y + (size_t)n * 200 + lane * 8);
    const __half2* yp = (const __half2*)&yv;
    __half2 o[4];
#pragma unroll
    for (int q = 0; q < 4; q++) {
        float2 fy = __half22float2(yp[q]);
        o[q] = __floats2half2_rn(fmaxf(acc[2 * q] * id + fy.x, 0.f),
                                 fmaxf(acc[2 * q + 1] * id + fy.y, 0.f));
    }
    *(uint4*)(hout + (size_t)n * 200 + lane * 8) = *(uint4*)o;
}

// ---------------- tf32 GEMM (projection head) --------------------------------
__device__ __forceinline__ unsigned f2tf(float f) {
    unsigned u;
    asm("cvt.rna.tf32.f32 %0, %1;" : "=r"(u) : "f"(f));
    return u;
}

__global__ void __launch_bounds__(256) gemm_tf32_kernel(
    const float* __restrict__ A0, const float* __restrict__ W0,
    const float* __restrict__ bias, float* __restrict__ C,
    int M, int N, int K)
{
    __shared__ unsigned As[128][36];
    __shared__ unsigned Bs[64][36];

    int tid = threadIdx.x;
    int wid = tid >> 5, lane = tid & 31;
    int wm = wid & 3, wn = wid >> 2;
    int lr = lane >> 2, lc = lane & 3;
    int m0 = blockIdx.x * 128, n0 = blockIdx.y * 64;

    float acc[2][4][4];
#pragma unroll
    for (int mt = 0; mt < 2; mt++)
#pragma unroll
        for (int nt = 0; nt < 4; nt++)
#pragma unroll
            for (int q = 0; q < 4; q++) acc[mt][nt][q] = 0.f;

    for (int k0 = 0; k0 < K; k0 += 32) {
#pragma unroll
        for (int i = 0; i < 16; i++) {
            int lin = tid + i * 256;
            int kk = lin & 31, row = lin >> 5;
            int m = m0 + row, k = k0 + kk;
            float v = (m < M && k < K) ? A0[(size_t)m * K + k] : 0.f;
            As[row][kk] = f2tf(v);
        }
#pragma unroll
        for (int i = 0; i < 8; i++) {
            int lin = tid + i * 256;
            int kk = lin & 31, row = lin >> 5;
            int n = n0 + row, k = k0 + kk;
            float v = (n < N && k < K) ? W0[(size_t)n * K + k] : 0.f;
            Bs[row][kk] = f2tf(v);
        }
        __syncthreads();

#pragma unroll
        for (int ks = 0; ks < 4; ks++) {
            unsigned a[2][4], b[4][2];
#pragma unroll
            for (int mt = 0; mt < 2; mt++) {
                int r = wm * 32 + mt * 16 + lr;
                a[mt][0] = As[r][ks * 8 + lc];
                a[mt][1] = As[r + 8][ks * 8 + lc];
                a[mt][2] = As[r][ks * 8 + lc + 4];
                a[mt][3] = As[r + 8][ks * 8 + lc + 4];
            }
#pragma unroll
            for (int nt = 0; nt < 4; nt++) {
                int n = wn * 32 + nt * 8 + lr;
                b[nt][0] = Bs[n][ks * 8 + lc];
                b[nt][1] = Bs[n][ks * 8 + lc + 4];
            }
#pragma unroll
            for (int mt = 0; mt < 2; mt++)
#pragma unroll
                for (int nt = 0; nt < 4; nt++) {
                    asm volatile(
                        "mma.sync.aligned.m16n8k8.row.col.f32.tf32.tf32.f32 "
                        "{%0,%1,%2,%3}, {%4,%5,%6,%7}, {%8,%9}, {%0,%1,%2,%3};"
                        : "+f"(acc[mt][nt][0]), "+f"(acc[mt][nt][1]),
                          "+f"(acc[mt][nt][2]), "+f"(acc[mt][nt][3])
                        : "r"(a[mt][0]), "r"(a[mt][1]), "r"(a[mt][2]), "r"(a[mt][3]),
                          "r"(b[nt][0]), "r"(b[nt][1]));
                }
        }
        __syncthreads();
    }

#pragma unroll
    for (int mt = 0; mt < 2; mt++) {
#pragma unroll
        for (int nt = 0; nt < 4; nt++) {
            int r = m0 + wm * 32 + mt * 16 + lr;
            int c = n0 + wn * 32 + nt * 8 + lc * 2;
#pragma unroll
            for (int q = 0; q < 4; q++) {
                int rr = r + (q >> 1) * 8;
                int cc = c + (q & 1);
                if (rr < M && cc < N)
                    C[(size_t)rr * N + cc] = acc[mt][nt][q] + bias[cc];
            }
        }
    }
}

// ---------------- standalone graph mean-pool (final layer) -------------------
__global__ void pool_kernel(const __half* __restrict__ h, const int* __restrict__ gstart,
                            const float* __restrict__ ginv, float* __restrict__ pool, int off)
{
    int g = blockIdx.x;
    int chunk = blockIdx.y;
    int f = threadIdx.x;
    if (f >= 200) return;
    int s0 = gstart[g], e0 = gstart[g + 1];
    int len = e0 - s0;
    if (len <= 0) return;
    int per = (len + 7) / 8;
    int s = s0 + chunk * per;
    int e = min(s + per, e0);
    if (s >= e) return;
    float acc = 0.f;
    for (int n = s; n < e; n++) acc += __half2float(h[(size_t)n * 200 + f]);
    atomicAdd(&pool[(size_t)g * 1000 + off + f], acc * ginv[g]);
}

// ---------------- final 250 -> 1 + sigmoid ----------------------------------
__global__ void mlp3_kernel(const float* __restrict__ in, const float* __restrict__ w,
                            const float* __restrict__ b, float* __restrict__ out)
{
    int g = threadIdx.x;
    float acc = b[0];
    for (int k = 0; k < 250; k++) acc += in[g * 250 + k] * w[k];
    out[g] = 1.0f / (1.0f + expf(-acc));
}

// ---------------- launch ----------------------------------------------------
extern "C" void kernel_launch(void* const* d_in, const int* in_sizes, int n_in,
                              void* d_out, int out_size)
{
    const float* x     = (const float*)d_in[0];
    const int*   ei    = (const int*)d_in[1];
    const int*   batch = (const int*)d_in[2];
    const float* Wl[5], *bl[5], *Wr[5];
    for (int i = 0; i < 5; i++) {
        Wl[i] = (const float*)d_in[3 + 3 * i];
        bl[i] = (const float*)d_in[4 + 3 * i];
        Wr[i] = (const float*)d_in[5 + 3 * i];
    }
    const float* pw1 = (const float*)d_in[18];
    const float* pb1 = (const float*)d_in[19];
    const float* pw2 = (const float*)d_in[20];
    const float* pb2 = (const float*)d_in[21];
    const float* pw3 = (const float*)d_in[22];
    const float* pb3 = (const float*)d_in[23];
    float* out = (float*)d_out;

    int E = in_sizes[1] / 2;
    const int* src = ei;
    const int* dst = ei + E;

    __half *hA, *hB, *zb, *yb, *xh, *aggh, *w16, *w1;
    float *invdeg, *pool, *m1, *m2, *ginv;
    int *gstart, *gcnt, *rowcnt, *rowptr, *cursor, *col, *bsum, *boff;
    cudaGetSymbolAddress((void**)&hA, g_hA);
    cudaGetSymbolAddress((void**)&hB, g_hB);
    cudaGetSymbolAddress((void**)&zb, g_z);
    cudaGetSymbolAddress((void**)&yb, g_y);
    cudaGetSymbolAddress((void**)&xh, g_xh);
    cudaGetSymbolAddress((void**)&aggh, g_aggh);
    cudaGetSymbolAddress((void**)&w16, g_w16);
    cudaGetSymbolAddress((void**)&w1, g_w1);
    cudaGetSymbolAddress((void**)&invdeg, g_invdeg);
    cudaGetSymbolAddress((void**)&pool, g_pool);
    cudaGetSymbolAddress((void**)&m1, g_m1);
    cudaGetSymbolAddress((void**)&m2, g_m2);
    cudaGetSymbolAddress((void**)&gstart, g_gstart);
    cudaGetSymbolAddress((void**)&gcnt, g_gcnt);
    cudaGetSymbolAddress((void**)&ginv, g_ginv);
    cudaGetSymbolAddress((void**)&rowcnt, g_rowcnt);
    cudaGetSymbolAddress((void**)&rowptr, g_rowptr);
    cudaGetSymbolAddress((void**)&cursor, g_cursor);
    cudaGetSymbolAddress((void**)&col, g_col);
    cudaGetSymbolAddress((void**)&bsum, g_bsum);
    cudaGetSymbolAddress((void**)&boff, g_boff);

    cudaMemsetAsync(rowcnt, 0, NN * sizeof(int));
    cudaMemsetAsync(gcnt, 0, NG * sizeof(int));
    cudaMemsetAsync(pool, 0, NG * 1000 * sizeof(float));

    // weight conversions + x padding
    {
        WPtrs p;
        for (int L = 1; L < 5; L++) {
            p.w[2 * (L - 1)]     = Wl[L];
            p.w[2 * (L - 1) + 1] = Wr[L];
        }
        dim3 wg((40000 + 255) / 256, 8);
        wconv_kernel<<<wg, 256>>>(p, w16);
        wconv1_kernel<<<(2 * 200 * 16 + 255) / 256, 256>>>(Wl[0], Wr[0], w1);
        xpad_kernel<<<(NN + 255) / 256, 256>>>(x, xh, NN);
    }

    // CSR build (by dst) + invdeg + graph segments
    count_kernel<<<(E + 255) / 256, 256>>>(dst, rowcnt, E);
    gcount_kernel<<<(NN + 255) / 256, 256>>>(batch, gcnt, NN);
    blockscan_kernel<<<NB_SCAN, 1024>>>(rowcnt, rowptr, bsum, NN);
    bsumscan_kernel<<<1, 128>>>(bsum, boff, NB_SCAN);
    apply_kernel<<<(NN + 255) / 256, 256>>>(rowcnt, rowptr, boff, cursor, invdeg, NN);
    fill_kernel<<<(E + 255) / 256, 256>>>(src, dst, cursor, col, E);
    gscan_kernel<<<1, 256>>>(gcnt, gstart, ginv);

    // ---- layer 1 (fp16 path, K=16) ----
    gather16_kernel<<<(NN + 127) / 128, 256>>>(rowptr, col, xh, invdeg, aggh, NN);
    {
        dim3 grid((NN + 127) / 128, 4);
        layer1_kernel<<<grid, 256>>>(aggh, xh, w1, w1 + 3200, bl[0], hA, NN);
    }

    // ---- layers 2-5: dual GEMM (+ fused pool) -> gather+combine ----
    cudaFuncSetAttribute(gemm_dual_kernel,
                         cudaFuncAttributeMaxDynamicSharedMemorySize, GD_SMEM);
    const __half* hin = hA;
    __half* hout = hB;
    for (int L = 1; L < 5; L++) {
        const __half* wl = w16 + (size_t)(L - 1) * 80000;
        const __half* wr = wl + 40000;
        dim3 grid((NN + 127) / 128, 5);
        gemm_dual_kernel<<<grid, 256, GD_SMEM>>>(hin, wl, wr, bl[L], zb, yb, NN,
                                                 gstart, ginv, pool, (L - 1) * 200);
        gather_combine_kernel<<<(NN + 9) / 10, 256>>>(rowptr, col, zb, yb, invdeg, hout, NN);
        const __half* t = hin;
        hin = hout;
        hout = (__half*)t;
    }
    // final layer's pool
    {
        dim3 pgrid(NG, 8);
        pool_kernel<<<pgrid, 256>>>(hin, gstart, ginv, pool, 800);
    }

    // ---- projection head (fp32/tf32) ----
    {
        dim3 g1((NG + 127) / 128, (500 + 63) / 64);
        gemm_tf32_kernel<<<g1, 256>>>(pool, pw1, pb1, m1, NG, 500, 1000);
        dim3 g2((NG + 127) / 128, (250 + 63) / 64);
        gemm_tf32_kernel<<<g2, 256>>>(m1, pw2, pb2, m2, NG, 250, 500);
        mlp3_kernel<<<1, 256>>>(m2, pw3, pb3, out);
    }
}

// round 17
// speedup vs baseline: 1.0913x; 1.0097x over previous
#include <cuda_runtime.h>
#include <cuda_fp16.h>
#include <stdint.h>
#include <math.h>

#define NN 100000
#define NG 256
#define MAXE 3400000
#define NB_SCAN ((NN + 1023) / 1024)
#define NB_APPLY ((NN + 255) / 256)

// ---------------- scratch (device globals; no allocations allowed) ----------
__device__ __half g_hA[(size_t)NN * 200];
__device__ __half g_hB[(size_t)NN * 200];
__device__ __half g_z [(size_t)NN * 200];
__device__ __half g_y [(size_t)NN * 200];
__device__ __half g_xh[(size_t)NN * 16];
__device__ __half g_aggh[(size_t)NN * 16];
__device__ __half g_w16[8 * 200 * 200];
__device__ __half g_w1[2 * 200 * 16];
__device__ float g_invdeg[NN];
__device__ float g_pool[NG * 1000];
__device__ float g_m1[NG * 500];
__device__ float g_m2[NG * 250];
__device__ int   g_gstart[NG + 1];
__device__ int   g_gcnt[NG];
__device__ float g_ginv[NG];
__device__ int   g_rowcnt[NN];
__device__ int   g_rowptr[NN + 1];
__device__ int   g_cursor[NN];
__device__ int   g_col[MAXE];
__device__ int   g_bsum[NB_SCAN];
__device__ int   g_boff[NB_SCAN];

// ---------------- small helpers ----------------------------------------------
__device__ __forceinline__ void cp16(uint32_t saddr, const void* gaddr, int sz) {
    asm volatile("cp.async.cg.shared.global [%0], [%1], 16, %2;"
                 :: "r"(saddr), "l"(gaddr), "r"(sz));
}
__device__ __forceinline__ void cp_commit() { asm volatile("cp.async.commit_group;"); }
__device__ __forceinline__ void ldm_x4(unsigned& r0, unsigned& r1, unsigned& r2, unsigned& r3,
                                       uint32_t addr) {
    asm volatile("ldmatrix.sync.aligned.m8n8.x4.shared.b16 {%0,%1,%2,%3}, [%4];"
                 : "=r"(r0), "=r"(r1), "=r"(r2), "=r"(r3) : "r"(addr));
}

// ---------- weight fp32 -> fp16 (layers 2-5 + layer-1 padded, one launch) ----
struct WPtrs { const float* w[8]; };
__global__ void wconv_kernel(WPtrs p, __half* __restrict__ o,
                             const float* __restrict__ Wl0, const float* __restrict__ Wr0,
                             __half* __restrict__ o1) {
    int which = blockIdx.y;
    int i = blockIdx.x * 256 + threadIdx.x;
    if (which < 8) {
        if (i < 40000) o[(size_t)which * 40000 + i] = __float2half(p.w[which][i]);
    } else {
        // layer-1 weights [200][11] -> [200][16] fp16 zero-padded (x2 matrices)
        if (i < 2 * 200 * 16) {
            int w = i / 3200, idx = i % 3200;
            int r = idx / 16, c = idx % 16;
            const float* W = w ? Wr0 : Wl0;
            o1[i] = __float2half(c < 11 ? W[r * 11 + c] : 0.f);
        }
    }
}

__global__ void xpad_kernel(const float* __restrict__ x, __half* __restrict__ xh, int n) {
    int i = blockIdx.x * 256 + threadIdx.x;
    if (i >= n) return;
    __half v[16];
#pragma unroll
    for (int c = 0; c < 11; c++) v[c] = __float2half(x[(size_t)i * 11 + c]);
#pragma unroll
    for (int c = 11; c < 16; c++) v[c] = __float2half(0.f);
    *(uint4*)(xh + (size_t)i * 16)     = *(uint4*)v;
    *(uint4*)(xh + (size_t)i * 16 + 8) = *(uint4*)(v + 8);
}

// ---------------- CSR build -------------------------------------------------
// merged edge-count (by dst) + graph-count (by batch), 1D grid over E+NN
__global__ void count_all_kernel(const int* __restrict__ dst, int* __restrict__ cnt, int E,
                                 const int* __restrict__ batch, int* __restrict__ gcnt, int n)
{
    int i = blockIdx.x * blockDim.x + threadIdx.x;
    if (i < E) {
        atomicAdd(&cnt[dst[i]], 1);
    } else {
        int j = i - E;
        if (j < n) atomicAdd(&gcnt[batch[j]], 1);
    }
}

__global__ void __launch_bounds__(1024) blockscan_kernel(
    const int* __restrict__ cnt, int* __restrict__ rowptr, int* __restrict__ bsum, int n)
{
    __shared__ int sh[1024];
    int tid = threadIdx.x;
    int i = blockIdx.x * 1024 + tid;
    int v = (i < n) ? cnt[i] : 0;
    sh[tid] = v;
    __syncthreads();
    for (int off = 1; off < 1024; off <<= 1) {
        int t = (tid >= off) ? sh[tid - off] : 0;
        __syncthreads();
        sh[tid] += t;
        __syncthreads();
    }
    if (i < n) rowptr[i + 1] = sh[tid];
    if (tid == 1023) bsum[blockIdx.x] = sh[1023];
}

__global__ void bsumscan_kernel(const int* __restrict__ bsum, int* __restrict__ boff, int nb) {
    __shared__ int sh[128];
    int tid = threadIdx.x;
    int v = (tid < nb) ? bsum[tid] : 0;
    sh[tid] = v;
    __syncthreads();
    for (int off = 1; off < 128; off <<= 1) {
        int t = (tid >= off) ? sh[tid - off] : 0;
        __syncthreads();
        sh[tid] += t;
        __syncthreads();
    }
    if (tid < nb) boff[tid] = sh[tid] - v;
}

// apply + fused graph-segment scan (extra last block; gcnt complete by now)
__global__ void apply_kernel(const int* __restrict__ cnt, int* __restrict__ rowptr,
                             const int* __restrict__ boff, int* __restrict__ cursor,
                             float* __restrict__ invdeg, int n,
                             const int* __restrict__ gcnt, int* __restrict__ gstart,
                             float* __restrict__ ginv)
{
    if (blockIdx.x == NB_APPLY) {
        if (threadIdx.x == 0) {
            int s = 0;
            for (int g = 0; g < NG; g++) { gstart[g] = s; s += gcnt[g]; }
            gstart[NG] = s;
        }
        __syncthreads();
        int g = threadIdx.x;
        if (g < NG) ginv[g] = 1.0f / (float)max(gcnt[g], 1);
        return;
    }
    int i = blockIdx.x * blockDim.x + threadIdx.x;
    if (i >= n) return;
    int total = rowptr[i + 1] + boff[i >> 10];
    rowptr[i + 1] = total;
    int c = cnt[i];
    cursor[i] = total - c;
    invdeg[i] = 1.0f / (float)max(c, 1);
    if (i == 0) rowptr[0] = 0;
}

__global__ void fill_kernel(const int* __restrict__ src, const int* __restrict__ dst,
                            int* __restrict__ cursor, int* __restrict__ col, int E) {
    int e = blockIdx.x * blockDim.x + threadIdx.x;
    if (e < E) {
        int d = dst[e];
        int pos = atomicAdd(&cursor[d], 1);
        col[pos] = src[e];
    }
}

// ---------------- 16-dim gather (layer 1, fp16) ------------------------------
__global__ void __launch_bounds__(256) gather16_kernel(
    const int* __restrict__ rowptr, const int* __restrict__ col,
    const __half* __restrict__ xh, const float* __restrict__ invdeg,
    __half* __restrict__ aggh, int nNodes)
{
    int t = threadIdx.x;
    int n = blockIdx.x * 128 + (t >> 1);
    if (n >= nNodes) return;
    int lane = t & 1;
    int s = rowptr[n], e = rowptr[n + 1];
    float acc[8];
#pragma unroll
    for (int q = 0; q < 8; q++) acc[q] = 0.f;
    for (int j = s; j < e; j++) {
        int c = __ldg(&col[j]);
        uint4 v = *(const uint4*)(xh + (size_t)c * 16 + lane * 8);
        const __half2* p = (const __half2*)&v;
#pragma unroll
        for (int q = 0; q < 4; q++) {
            float2 f = __half22float2(p[q]);
            acc[2 * q]     += f.x;
            acc[2 * q + 1] += f.y;
        }
    }
    float id = invdeg[n];
    __half2 o[4];
#pragma unroll
    for (int q = 0; q < 4; q++)
        o[q] = __floats2half2_rn(acc[2 * q] * id, acc[2 * q + 1] * id);
    *(uint4*)(aggh + (size_t)n * 16 + lane * 8) = *(uint4*)o;
}

// ---------------- layer-1 GEMM: dual-source K=16 fp16 MMA --------------------
#define L1S 24
__global__ void __launch_bounds__(256) layer1_kernel(
    const __half* __restrict__ A0, const __half* __restrict__ A1,
    const __half* __restrict__ W0, const __half* __restrict__ W1,
    const float* __restrict__ bias, __half* __restrict__ C, int M)
{
    const int N = 200;
    __shared__ __half As0[128][L1S], As1[128][L1S];
    __shared__ __half Bs0[64][L1S],  Bs1[64][L1S];

    int tid = threadIdx.x;
    int wid = tid >> 5, lane = tid & 31;
    int wm = wid & 3, wn = wid >> 2;
    int lr = lane >> 2, lc = lane & 3;
    int m0 = blockIdx.x * 128, n0 = blockIdx.y * 64;

    {
        int kq = tid & 1, row = tid >> 1;
        int m = m0 + row;
        uint4 v0 = make_uint4(0,0,0,0), v1 = v0;
        if (m < M) {
            v0 = *(const uint4*)(A0 + (size_t)m * 16 + kq * 8);
            v1 = *(const uint4*)(A1 + (size_t)m * 16 + kq * 8);
        }
        *(uint4*)&As0[row][kq * 8] = v0;
        *(uint4*)&As1[row][kq * 8] = v1;
    }
    {
        int lin = tid;
        int which = lin >> 7;
        int idx = lin & 127;
        int kq = idx & 1, row = idx >> 1;
        int n = n0 + row;
        uint4 v = make_uint4(0,0,0,0);
        const __half* W = which ? W1 : W0;
        if (n < N) v = *(const uint4*)(W + (size_t)n * 16 + kq * 8);
        if (which) *(uint4*)&Bs1[row][kq * 8] = v;
        else       *(uint4*)&Bs0[row][kq * 8] = v;
    }
    __syncthreads();

    float acc[2][4][4];
#pragma unroll
    for (int mt = 0; mt < 2; mt++)
#pragma unroll
        for (int nt = 0; nt < 4; nt++)
#pragma unroll
            for (int q = 0; q < 4; q++) acc[mt][nt][q] = 0.f;

#pragma unroll
    for (int sidx = 0; sidx < 2; sidx++) {
        unsigned a[2][4], b[4][2];
#pragma unroll
        for (int mt = 0; mt < 2; mt++) {
            int r = wm * 32 + mt * 16 + lr;
            const __half (*As)[L1S] = sidx ? As1 : As0;
            a[mt][0] = *(const unsigned*)&As[r][lc * 2];
            a[mt][1] = *(const unsigned*)&As[r + 8][lc * 2];
            a[mt][2] = *(const unsigned*)&As[r][lc * 2 + 8];
            a[mt][3] = *(const unsigned*)&As[r + 8][lc * 2 + 8];
        }
#pragma unroll
        for (int nt = 0; nt < 4; nt++) {
            int n = wn * 32 + nt * 8 + lr;
            const __half (*Bs)[L1S] = sidx ? Bs1 : Bs0;
            b[nt][0] = *(const unsigned*)&Bs[n][lc * 2];
            b[nt][1] = *(const unsigned*)&Bs[n][lc * 2 + 8];
        }
#pragma unroll
        for (int mt = 0; mt < 2; mt++)
#pragma unroll
            for (int nt = 0; nt < 4; nt++) {
                asm volatile(
                    "mma.sync.aligned.m16n8k16.row.col.f32.f16.f16.f32 "
                    "{%0,%1,%2,%3}, {%4,%5,%6,%7}, {%8,%9}, {%0,%1,%2,%3};"
                    : "+f"(acc[mt][nt][0]), "+f"(acc[mt][nt][1]),
                      "+f"(acc[mt][nt][2]), "+f"(acc[mt][nt][3])
                    : "r"(a[mt][0]), "r"(a[mt][1]), "r"(a[mt][2]), "r"(a[mt][3]),
                      "r"(b[nt][0]), "r"(b[nt][1]));
            }
    }

#pragma unroll
    for (int mt = 0; mt < 2; mt++) {
#pragma unroll
        for (int nt = 0; nt < 4; nt++) {
            int r = m0 + wm * 32 + mt * 16 + lr;
            int c = n0 + wn * 32 + nt * 8 + lc * 2;
            if (c < N) {
                float b0 = bias[c], b1 = bias[c + 1 < N ? c + 1 : c];
                if (r < M) {
                    __half2 v = __floats2half2_rn(fmaxf(acc[mt][nt][0] + b0, 0.f),
                                                  fmaxf(acc[mt][nt][1] + b1, 0.f));
                    *(__half2*)(C + (size_t)r * N + c) = v;
                }
                if (r + 8 < M) {
                    __half2 v = __floats2half2_rn(fmaxf(acc[mt][nt][2] + b0, 0.f),
                                                  fmaxf(acc[mt][nt][3] + b1, 0.f));
                    *(__half2*)(C + (size_t)(r + 8) * N + c) = v;
                }
            }
        }
    }
}

// ---------------- 3-stage pipelined dual-output GEMM + fused pool ------------
#define DBS 40
#define GD_SZA (128 * DBS * 2)
#define GD_SZB (64 * DBS * 2)
#define GD_BOFF (3 * GD_SZA)
#define GD_SMEM (3 * GD_SZA + 3 * 2 * GD_SZB)
__global__ void __launch_bounds__(256) gemm_dual_kernel(
    const __half* __restrict__ A,
    const __half* __restrict__ W0, const __half* __restrict__ W1,
    const float* __restrict__ bias,
    __half* __restrict__ Z, __half* __restrict__ Y, int M,
    const int* __restrict__ gstart, const float* __restrict__ ginv,
    float* __restrict__ pool, int poff)
{
    const int N = 200, K = 200, NIT = 7;
    int tid = threadIdx.x;

    if (blockIdx.y == 4) {
        int pb = blockIdx.x;
        if (pb >= NG * 3) return;
        int g = pb & 255, chunk = pb >> 8;
        int f = tid;
        if (f >= 200) return;
        int s0 = gstart[g], e0 = gstart[g + 1];
        int len = e0 - s0;
        if (len <= 0) return;
        int per = (len + 2) / 3;
        int s = s0 + chunk * per;
        int e = min(s + per, e0);
        if (s >= e) return;
        float acc = 0.f;
        for (int n = s; n < e; n++) acc += __half2float(A[(size_t)n * 200 + f]);
        atomicAdd(&pool[(size_t)g * 1000 + poff + f], acc * ginv[g]);
        return;
    }

    extern __shared__ __half dynsmem[];
    int wid = tid >> 5, lane = tid & 31;
    int wm = wid & 3, wn = wid >> 2;
    int lr = lane >> 2, lc = lane & 3;
    int m0 = blockIdx.x * 128, n0 = blockIdx.y * 64;

    uint32_t sBase = (uint32_t)__cvta_generic_to_shared(dynsmem);

    float accZ[2][4][4], accY[2][4][4];
#pragma unroll
    for (int mt = 0; mt < 2; mt++)
#pragma unroll
        for (int nt = 0; nt < 4; nt++)
#pragma unroll
            for (int q = 0; q < 4; q++) { accZ[mt][nt][q] = 0.f; accY[mt][nt][q] = 0.f; }

    uint32_t offA[2];
#pragma unroll
    for (int mt = 0; mt < 2; mt++)
        offA[mt] = ((wm * 32 + mt * 16 + (lane & 15)) * DBS + (lane >> 4) * 8) * 2;
    uint32_t offB[2];
#pragma unroll
    for (int p = 0; p < 2; p++)
        offB[p] = ((wn * 32 + p * 16 + (lane & 7) + ((lane >> 4) << 3)) * DBS
                   + ((lane >> 3) & 1) * 8) * 2;

    auto stage = [&](int buf, int k0) {
#pragma unroll
        for (int i = 0; i < 2; i++) {
            int lin = tid + i * 256;
            int kq = lin & 3, row = lin >> 2;
            int m = m0 + row, k = k0 + kq * 8;
            bool ok = (m < M) && (k < K);
            const __half* gp = A + (ok ? ((size_t)m * K + k) : 0);
            cp16(sBase + buf * GD_SZA + (row * DBS + kq * 8) * 2, gp, ok ? 16 : 0);
        }
        {
            int kq = tid & 3, row = tid >> 2;
            int n = n0 + row, k = k0 + kq * 8;
            bool ok = (n < N) && (k < K);
            const __half* gp0 = W0 + (ok ? ((size_t)n * K + k) : 0);
            const __half* gp1 = W1 + (ok ? ((size_t)n * K + k) : 0);
            uint32_t bb = sBase + GD_BOFF + buf * 2 * GD_SZB;
            cp16(bb + (row * DBS + kq * 8) * 2, gp0, ok ? 16 : 0);
            cp16(bb + GD_SZB + (row * DBS + kq * 8) * 2, gp1, ok ? 16 : 0);
        }
        cp_commit();
    };

    stage(0, 0);
    stage(1, 32);

    for (int it = 0; it < NIT; it++) {
        if (it + 1 < NIT) asm volatile("cp.async.wait_group 1;");
        else              asm volatile("cp.async.wait_group 0;");
        __syncthreads();
        if (it + 2 < NIT) stage((it + 2) % 3, (it + 2) * 32);

        int buf = it % 3;
        uint32_t aBase = sBase + buf * GD_SZA;
        uint32_t bBase0 = sBase + GD_BOFF + buf * 2 * GD_SZB;
        uint32_t bBase1 = bBase0 + GD_SZB;

#pragma unroll
        for (int ks = 0; ks < 2; ks++) {
            int koB = ks * 32;
            unsigned a[2][4], bZ[4][2], bY[4][2];
#pragma unroll
            for (int mt = 0; mt < 2; mt++)
                ldm_x4(a[mt][0], a[mt][1], a[mt][2], a[mt][3], aBase + offA[mt] + koB);
#pragma unroll
            for (int p = 0; p < 2; p++) {
                ldm_x4(bZ[2*p][0], bZ[2*p][1], bZ[2*p+1][0], bZ[2*p+1][1],
                       bBase0 + offB[p] + koB);
                ldm_x4(bY[2*p][0], bY[2*p][1], bY[2*p+1][0], bY[2*p+1][1],
                       bBase1 + offB[p] + koB);
            }
#pragma unroll
            for (int mt = 0; mt < 2; mt++)
#pragma unroll
                for (int nt = 0; nt < 4; nt++) {
                    asm volatile(
                        "mma.sync.aligned.m16n8k16.row.col.f32.f16.f16.f32 "
                        "{%0,%1,%2,%3}, {%4,%5,%6,%7}, {%8,%9}, {%0,%1,%2,%3};"
                        : "+f"(accZ[mt][nt][0]), "+f"(accZ[mt][nt][1]),
                          "+f"(accZ[mt][nt][2]), "+f"(accZ[mt][nt][3])
                        : "r"(a[mt][0]), "r"(a[mt][1]), "r"(a[mt][2]), "r"(a[mt][3]),
                          "r"(bZ[nt][0]), "r"(bZ[nt][1]));
                    asm volatile(
                        "mma.sync.aligned.m16n8k16.row.col.f32.f16.f16.f32 "
                        "{%0,%1,%2,%3}, {%4,%5,%6,%7}, {%8,%9}, {%0,%1,%2,%3};"
                        : "+f"(accY[mt][nt][0]), "+f"(accY[mt][nt][1]),
                          "+f"(accY[mt][nt][2]), "+f"(accY[mt][nt][3])
                        : "r"(a[mt][0]), "r"(a[mt][1]), "r"(a[mt][2]), "r"(a[mt][3]),
                          "r"(bY[nt][0]), "r"(bY[nt][1]));
                }
        }
    }

#pragma unroll
    for (int mt = 0; mt < 2; mt++) {
#pragma unroll
        for (int nt = 0; nt < 4; nt++) {
            int r = m0 + wm * 32 + mt * 16 + lr;
            int c = n0 + wn * 32 + nt * 8 + lc * 2;
            if (c < N) {
                float b0 = bias[c], b1 = bias[c + 1 < N ? c + 1 : c];
                if (r < M) {
                    *(__half2*)(Z + (size_t)r * N + c) =
                        __floats2half2_rn(accZ[mt][nt][0], accZ[mt][nt][1]);
                    *(__half2*)(Y + (size_t)r * N + c) =
                        __floats2half2_rn(accY[mt][nt][0] + b0, accY[mt][nt][1] + b1);
                }
                if (r + 8 < M) {
                    *(__half2*)(Z + (size_t)(r + 8) * N + c) =
                        __floats2half2_rn(accZ[mt][nt][2], accZ[mt][nt][3]);
                    *(__half2*)(Y + (size_t)(r + 8) * N + c) =
                        __floats2half2_rn(accY[mt][nt][2] + b0, accY[mt][nt][3] + b1);
                }
            }
        }
    }
}

// ---------------- gather + combine: hout = relu(mean(z[nbrs]) + y) ----------
__global__ void __launch_bounds__(256) gather_combine_kernel(
    const int* __restrict__ rowptr, const int* __restrict__ col,
    const __half* __restrict__ z, const __half* __restrict__ y,
    const float* __restrict__ invdeg, __half* __restrict__ hout, int nNodes)
{
    int t = threadIdx.x;
    if (t >= 250) return;
    int n = blockIdx.x * 10 + t / 25;
    if (n >= nNodes) return;
    int lane = t % 25;
    int s = rowptr[n], e = rowptr[n + 1];
    float acc[8];
#pragma unroll
    for (int q = 0; q < 8; q++) acc[q] = 0.f;
    int j = s;
    for (; j + 3 < e; j += 4) {
        int c0 = __ldg(&col[j]);
        int c1 = __ldg(&col[j + 1]);
        int c2 = __ldg(&col[j + 2]);
        int c3 = __ldg(&col[j + 3]);
        uint4 v0 = *(const uint4*)(z + (size_t)c0 * 200 + lane * 8);
        uint4 v1 = *(const uint4*)(z + (size_t)c1 * 200 + lane * 8);
        uint4 v2 = *(const uint4*)(z + (size_t)c2 * 200 + lane * 8);
        uint4 v3 = *(const uint4*)(z + (size_t)c3 * 200 + lane * 8);
        const __half2* p0 = (const __half2*)&v0;
        const __half2* p1 = (const __half2*)&v1;
        const __half2* p2 = (const __half2*)&v2;
        const __half2* p3 = (const __half2*)&v3;
#pragma unroll
        for (int q = 0; q < 4; q++) {
            float2 f0 = __half22float2(p0[q]);
            float2 f1 = __half22float2(p1[q]);
            float2 f2 = __half22float2(p2[q]);
            float2 f3 = __half22float2(p3[q]);
            acc[2 * q]     += (f0.x + f1.x) + (f2.x + f3.x);
            acc[2 * q + 1] += (f0.y + f1.y) + (f2.y + f3.y);
        }
    }
    for (; j < e; j++) {
        int c0 = __ldg(&col[j]);
        uint4 v0 = *(const uint4*)(z + (size_t)c0 * 200 + lane * 8);
        const __half2* p0 = (const __half2*)&v0;
#pragma unroll
        for (int q = 0; q < 4; q++) {
            float2 f0 = __half22float2(p0[q]);
            acc[2 * q]     += f0.x;
            acc[2 * q + 1] += f0.y;
        }
    }
    float id = invdeg[n];
    uint4 yv = *(const uint4*)(y + (size_t)n * 200 + lane * 8);
    const __half2* yp = (const __half2*)&yv;
    __half2 o[4];
#pragma unroll
    for (int q = 0; q < 4; q++) {
        float2 fy = __half22float2(yp[q]);
        o[q] = __floats2half2_rn(fmaxf(acc[2 * q] * id + fy.x, 0.f),
                                 fmaxf(acc[2 * q + 1] * id + fy.y, 0.f));
    }
    *(uint4*)(hout + (size_t)n * 200 + lane * 8) = *(uint4*)o;
}

// ---------------- tf32 GEMM (projection head) --------------------------------
__device__ __forceinline__ unsigned f2tf(float f) {
    unsigned u;
    asm("cvt.rna.tf32.f32 %0, %1;" : "=r"(u) : "f"(f));
    return u;
}

__global__ void __launch_bounds__(256) gemm_tf32_kernel(
    const float* __restrict__ A0, const float* __restrict__ W0,
    const float* __restrict__ bias, float* __restrict__ C,
    int M, int N, int K)
{
    __shared__ unsigned As[128][36];
    __shared__ unsigned Bs[64][36];

    int tid = threadIdx.x;
    int wid = tid >> 5, lane = tid & 31;
    int wm = wid & 3, wn = wid >> 2;
    int lr = lane >> 2, lc = lane & 3;
    int m0 = blockIdx.x * 128, n0 = blockIdx.y * 64;

    float acc[2][4][4];
#pragma unroll
    for (int mt = 0; mt < 2; mt++)
#pragma unroll
        for (int nt = 0; nt < 4; nt++)
#pragma unroll
            for (int q = 0; q < 4; q++) acc[mt][nt][q] = 0.f;

    for (int k0 = 0; k0 < K; k0 += 32) {
#pragma unroll
        for (int i = 0; i < 16; i++) {
            int lin = tid + i * 256;
            int kk = lin & 31, row = lin >> 5;
            int m = m0 + row, k = k0 + kk;
            float v = (m < M && k < K) ? A0[(size_t)m * K + k] : 0.f;
            As[row][kk] = f2tf(v);
        }
#pragma unroll
        for (int i = 0; i < 8; i++) {
            int lin = tid + i * 256;
            int kk = lin & 31, row = lin >> 5;
            int n = n0 + row, k = k0 + kk;
            float v = (n < N && k < K) ? W0[(size_t)n * K + k] : 0.f;
            Bs[row][kk] = f2tf(v);
        }
        __syncthreads();

#pragma unroll
        for (int ks = 0; ks < 4; ks++) {
            unsigned a[2][4], b[4][2];
#pragma unroll
            for (int mt = 0; mt < 2; mt++) {
                int r = wm * 32 + mt * 16 + lr;
                a[mt][0] = As[r][ks * 8 + lc];
                a[mt][1] = As[r + 8][ks * 8 + lc];
                a[mt][2] = As[r][ks * 8 + lc + 4];
                a[mt][3] = As[r + 8][ks * 8 + lc + 4];
            }
#pragma unroll
            for (int nt = 0; nt < 4; nt++) {
                int n = wn * 32 + nt * 8 + lr;
                b[nt][0] = Bs[n][ks * 8 + lc];
                b[nt][1] = Bs[n][ks * 8 + lc + 4];
            }
#pragma unroll
            for (int mt = 0; mt < 2; mt++)
#pragma unroll
                for (int nt = 0; nt < 4; nt++) {
                    asm volatile(
                        "mma.sync.aligned.m16n8k8.row.col.f32.tf32.tf32.f32 "
                        "{%0,%1,%2,%3}, {%4,%5,%6,%7}, {%8,%9}, {%0,%1,%2,%3};"
                        : "+f"(acc[mt][nt][0]), "+f"(acc[mt][nt][1]),
                          "+f"(acc[mt][nt][2]), "+f"(acc[mt][nt][3])
                        : "r"(a[mt][0]), "r"(a[mt][1]), "r"(a[mt][2]), "r"(a[mt][3]),
                          "r"(b[nt][0]), "r"(b[nt][1]));
                }
        }
        __syncthreads();
    }

#pragma unroll
    for (int mt = 0; mt < 2; mt++) {
#pragma unroll
        for (int nt = 0; nt < 4; nt++) {
            int r = m0 + wm * 32 + mt * 16 + lr;
            int c = n0 + wn * 32 + nt * 8 + lc * 2;
#pragma unroll
            for (int q = 0; q < 4; q++) {
                int rr = r + (q >> 1) * 8;
                int cc = c + (q & 1);
                if (rr < M && cc < N)
                    C[(size_t)rr * N + cc] = acc[mt][nt][q] + bias[cc];
            }
        }
    }
}

// ---------------- standalone graph mean-pool (final layer) -------------------
__global__ void pool_kernel(const __half* __restrict__ h, const int* __restrict__ gstart,
                            const float* __restrict__ ginv, float* __restrict__ pool, int off)
{
    int g = blockIdx.x;
    int chunk = blockIdx.y;
    int f = threadIdx.x;
    if (f >= 200) return;
    int s0 = gstart[g], e0 = gstart[g + 1];
    int len = e0 - s0;
    if (len <= 0) return;
    int per = (len + 7) / 8;
    int s = s0 + chunk * per;
    int e = min(s + per, e0);
    if (s >= e) return;
    float acc = 0.f;
    for (int n = s; n < e; n++) acc += __half2float(h[(size_t)n * 200 + f]);
    atomicAdd(&pool[(size_t)g * 1000 + off + f], acc * ginv[g]);
}

// ---------------- final 250 -> 1 + sigmoid ----------------------------------
__global__ void mlp3_kernel(const float* __restrict__ in, const float* __restrict__ w,
                            const float* __restrict__ b, float* __restrict__ out)
{
    int g = threadIdx.x;
    float acc = b[0];
    for (int k = 0; k < 250; k++) acc += in[g * 250 + k] * w[k];
    out[g] = 1.0f / (1.0f + expf(-acc));
}

// ---------------- launch ----------------------------------------------------
extern "C" void kernel_launch(void* const* d_in, const int* in_sizes, int n_in,
                              void* d_out, int out_size)
{
    const float* x     = (const float*)d_in[0];
    const int*   ei    = (const int*)d_in[1];
    const int*   batch = (const int*)d_in[2];
    const float* Wl[5], *bl[5], *Wr[5];
    for (int i = 0; i < 5; i++) {
        Wl[i] = (const float*)d_in[3 + 3 * i];
        bl[i] = (const float*)d_in[4 + 3 * i];
        Wr[i] = (const float*)d_in[5 + 3 * i];
    }
    const float* pw1 = (const float*)d_in[18];
    const float* pb1 = (const float*)d_in[19];
    const float* pw2 = (const float*)d_in[20];
    const float* pb2 = (const float*)d_in[21];
    const float* pw3 = (const float*)d_in[22];
    const float* pb3 = (const float*)d_in[23];
    float* out = (float*)d_out;

    int E = in_sizes[1] / 2;
    const int* src = ei;
    const int* dst = ei + E;

    __half *hA, *hB, *zb, *yb, *xh, *aggh, *w16, *w1;
    float *invdeg, *pool, *m1, *m2, *ginv;
    int *gstart, *gcnt, *rowcnt, *rowptr, *cursor, *col, *bsum, *boff;
    cudaGetSymbolAddress((void**)&hA, g_hA);
    cudaGetSymbolAddress((void**)&hB, g_hB);
    cudaGetSymbolAddress((void**)&zb, g_z);
    cudaGetSymbolAddress((void**)&yb, g_y);
    cudaGetSymbolAddress((void**)&xh, g_xh);
    cudaGetSymbolAddress((void**)&aggh, g_aggh);
    cudaGetSymbolAddress((void**)&w16, g_w16);
    cudaGetSymbolAddress((void**)&w1, g_w1);
    cudaGetSymbolAddress((void**)&invdeg, g_invdeg);
    cudaGetSymbolAddress((void**)&pool, g_pool);
    cudaGetSymbolAddress((void**)&m1, g_m1);
    cudaGetSymbolAddress((void**)&m2, g_m2);
    cudaGetSymbolAddress((void**)&gstart, g_gstart);
    cudaGetSymbolAddress((void**)&gcnt, g_gcnt);
    cudaGetSymbolAddress((void**)&ginv, g_ginv);
    cudaGetSymbolAddress((void**)&rowcnt, g_rowcnt);
    cudaGetSymbolAddress((void**)&rowptr, g_rowptr);
    cudaGetSymbolAddress((void**)&cursor, g_cursor);
    cudaGetSymbolAddress((void**)&col, g_col);
    cudaGetSymbolAddress((void**)&bsum, g_bsum);
    cudaGetSymbolAddress((void**)&boff, g_boff);

    cudaMemsetAsync(rowcnt, 0, NN * sizeof(int));
    cudaMemsetAsync(gcnt, 0, NG * sizeof(int));
    cudaMemsetAsync(pool, 0, NG * 1000 * sizeof(float));

    // weight conversions (all 10 matrices, one launch) + x padding
    {
        WPtrs p;
        for (int L = 1; L < 5; L++) {
            p.w[2 * (L - 1)]     = Wl[L];
            p.w[2 * (L - 1) + 1] = Wr[L];
        }
        dim3 wg((40000 + 255) / 256, 9);
        wconv_kernel<<<wg, 256>>>(p, w16, Wl[0], Wr[0], w1);
        xpad_kernel<<<(NN + 255) / 256, 256>>>(x, xh, NN);
    }

    // CSR build (by dst) + invdeg + graph segments (count+gcount merged;
    // gscan fused into apply as its extra last block)
    count_all_kernel<<<(E + NN + 255) / 256, 256>>>(dst, rowcnt, E, batch, gcnt, NN);
    blockscan_kernel<<<NB_SCAN, 1024>>>(rowcnt, rowptr, bsum, NN);
    bsumscan_kernel<<<1, 128>>>(bsum, boff, NB_SCAN);
    apply_kernel<<<NB_APPLY + 1, 256>>>(rowcnt, rowptr, boff, cursor, invdeg, NN,
                                        gcnt, gstart, ginv);
    fill_kernel<<<(E + 255) / 256, 256>>>(src, dst, cursor, col, E);

    // ---- layer 1 (fp16 path, K=16) ----
    gather16_kernel<<<(NN + 127) / 128, 256>>>(rowptr, col, xh, invdeg, aggh, NN);
    {
        dim3 grid((NN + 127) / 128, 4);
        layer1_kernel<<<grid, 256>>>(aggh, xh, w1, w1 + 3200, bl[0], hA, NN);
    }

    // ---- layers 2-5: dual GEMM (+ fused pool) -> gather+combine ----
    cudaFuncSetAttribute(gemm_dual_kernel,
                         cudaFuncAttributeMaxDynamicSharedMemorySize, GD_SMEM);
    const __half* hin = hA;
    __half* hout = hB;
    for (int L = 1; L < 5; L++) {
        const __half* wl = w16 + (size_t)(L - 1) * 80000;
        const __half* wr = wl + 40000;
        dim3 grid((NN + 127) / 128, 5);
        gemm_dual_kernel<<<grid, 256, GD_SMEM>>>(hin, wl, wr, bl[L], zb, yb, NN,
                                                 gstart, ginv, pool, (L - 1) * 200);
        gather_combine_kernel<<<(NN + 9) / 10, 256>>>(rowptr, col, zb, yb, invdeg, hout, NN);
        const __half* t = hin;
        hin = hout;
        hout = (__half*)t;
    }
    // final layer's pool
    {
        dim3 pgrid(NG, 8);
        pool_kernel<<<pgrid, 256>>>(hin, gstart, ginv, pool, 800);
    }

    // ---- projection head (fp32/tf32) ----
    {
        dim3 g1((NG + 127) / 128, (500 + 63) / 64);
        gemm_tf32_kernel<<<g1, 256>>>(pool, pw1, pb1, m1, NG, 500, 1000);
        dim3 g2((NG + 127) / 128, (250 + 63) / 64);
        gemm_tf32_kernel<<<g2, 256>>>(m1, pw2, pb2, m2, NG, 250, 500);
        mlp3_kernel<<<1, 256>>>(m2, pw3, pb3, out);
    }
}